// round 2
// baseline (speedup 1.0000x reference)
#include <cuda_runtime.h>
#include <math.h>

#define VN 50257
#define KN 512
#define DN 768
#define RN 192
#define KD 960   // DN + RN

// ---------------- scratch (static device globals; no allocation) ----------------
__device__ float g_Acat[KN * KD];       // [K, 960] = [a_norm | U^T a]
__device__ float g_Bcat[VN * KD];       // [V, 960] = [w_norm | U^T w]
__device__ float g_AA[KN];
__device__ float g_BB[VN];
__device__ float g_base[KN * VN];       // scale*s + bias - 0.3*mahal
__device__ float g_logK[KN * VN];       // -mahal/eps
__device__ float g_lu[KN];
__device__ float g_lv[VN];
__device__ float g_rowm[KN];
__device__ float g_rows[KN];
__device__ int   g_idflag;

// ---------------- init: zero log_v, set identity flag ----------------
__global__ void k_init() {
    int i = blockIdx.x * blockDim.x + threadIdx.x;
    if (i < VN) g_lv[i] = 0.f;
    if (i == 0) g_idflag = 1;
}

// ---------------- identity check on word_proj_w ----------------
__global__ void k_idcheck(const float* __restrict__ Wp) {
    int stride = gridDim.x * blockDim.x;
    for (int i = blockIdx.x * blockDim.x + threadIdx.x; i < DN * DN; i += stride) {
        float e = ((i / DN) == (i % DN)) ? 1.f : 0.f;
        if (Wp[i] != e) g_idflag = 0;   // benign race: all writers store 0
    }
}

// ---------------- anchors: normalize, Ua = a@U, AA ----------------
__global__ void k_anchors(const float* __restrict__ anch, const float* __restrict__ U) {
    __shared__ float sa[DN];
    __shared__ float sred[256];
    __shared__ float sua[RN];
    int k = blockIdx.x, tid = threadIdx.x;

    float ss = 0.f;
    for (int d = tid; d < DN; d += 256) { float x = anch[k * DN + d]; sa[d] = x; ss += x * x; }
    sred[tid] = ss; __syncthreads();
    for (int o = 128; o > 0; o >>= 1) { if (tid < o) sred[tid] += sred[tid + o]; __syncthreads(); }
    float inv = 1.f / fmaxf(sqrtf(sred[0]), 1e-12f);
    __syncthreads();
    for (int d = tid; d < DN; d += 256) { float x = sa[d] * inv; sa[d] = x; g_Acat[k * KD + d] = x; }
    __syncthreads();
    if (tid < RN) {
        float acc = 0.f;
        for (int d = 0; d < DN; d++) acc += sa[d] * U[d * RN + tid];
        g_Acat[k * KD + DN + tid] = acc;
        sua[tid] = acc;
    }
    __syncthreads();
    float aa = 0.f;
    for (int r = tid; r < RN; r += 256) aa += sua[r] * sua[r];
    sred[tid] = aa; __syncthreads();
    for (int o = 128; o > 0; o >>= 1) { if (tid < o) sred[tid] += sred[tid + o]; __syncthreads(); }
    if (tid == 0) g_AA[k] = 1.f + sred[0];
}

// ---------------- w_norm: (optional projection) + normalize ----------------
__global__ void k_wnorm(const float* __restrict__ we, const float* __restrict__ Wp) {
    __shared__ float se[DN];
    __shared__ float sw[DN];
    __shared__ float sred[256];
    int v = blockIdx.x, tid = threadIdx.x;
    int flag = g_idflag;

    for (int d = tid; d < DN; d += 256) se[d] = we[v * DN + d];
    __syncthreads();
    if (flag) {
        for (int d = tid; d < DN; d += 256) sw[d] = se[d];
    } else {
        // w[v,d] = sum_j we[v,j] * Wp[d,j]   (slow fallback; not hit for this dataset)
        for (int d = tid; d < DN; d += 256) {
            float acc = 0.f;
            for (int j = 0; j < DN; j++) acc += se[j] * Wp[d * DN + j];
            sw[d] = acc;
        }
    }
    __syncthreads();
    float ss = 0.f;
    for (int d = tid; d < DN; d += 256) { float x = sw[d]; ss += x * x; }
    sred[tid] = ss; __syncthreads();
    for (int o = 128; o > 0; o >>= 1) { if (tid < o) sred[tid] += sred[tid + o]; __syncthreads(); }
    float inv = 1.f / fmaxf(sqrtf(sred[0]), 1e-12f);
    for (int d = tid; d < DN; d += 256) g_Bcat[v * KD + d] = sw[d] * inv;
}

// ---------------- Ub = w_norm @ U : tiled GEMM [V,768]x[768,192] ----------------
#define UB_BM 64
__global__ __launch_bounds__(256) void k_ubgemm(const float* __restrict__ U) {
    __shared__ float As[UB_BM][9];      // +1 pad
    __shared__ float Bs[8][RN];
    int bm = blockIdx.x * UB_BM;
    int tid = threadIdx.x, tx = tid % 16, ty = tid / 16;
    float acc[4][12];
    #pragma unroll
    for (int r = 0; r < 4; r++)
        #pragma unroll
        for (int c = 0; c < 12; c++) acc[r][c] = 0.f;

    for (int k0 = 0; k0 < DN; k0 += 8) {
        for (int i = tid; i < UB_BM * 8; i += 256) {
            int kk = i % 8, mm = i / 8, row = bm + mm;
            As[mm][kk] = (row < VN) ? g_Bcat[row * KD + k0 + kk] : 0.f;
        }
        for (int i = tid; i < 8 * RN; i += 256) {
            int n = i % RN, kk = i / RN;
            Bs[kk][n] = U[(k0 + kk) * RN + n];
        }
        __syncthreads();
        #pragma unroll
        for (int kk = 0; kk < 8; kk++) {
            float a[4], b[12];
            #pragma unroll
            for (int r = 0; r < 4; r++) a[r] = As[ty * 4 + r][kk];
            #pragma unroll
            for (int c = 0; c < 12; c++) b[c] = Bs[kk][tx * 12 + c];
            #pragma unroll
            for (int r = 0; r < 4; r++)
                #pragma unroll
                for (int c = 0; c < 12; c++) acc[r][c] += a[r] * b[c];
        }
        __syncthreads();
    }
    #pragma unroll
    for (int r = 0; r < 4; r++) {
        int row = bm + ty * 4 + r;
        if (row < VN)
            #pragma unroll
            for (int c = 0; c < 12; c++)
                g_Bcat[row * KD + DN + tx * 12 + c] = acc[r][c];
    }
}

// ---------------- BB[v] = 1 + ||Ub_v||^2 ----------------
__global__ void k_bb() {
    int v = blockIdx.x * blockDim.x + threadIdx.x;
    if (v >= VN) return;
    const float* p = &g_Bcat[v * KD + DN];
    float s = 0.f;
    #pragma unroll 8
    for (int r = 0; r < RN; r++) { float x = p[r]; s += x * x; }
    g_BB[v] = 1.f + s;
}

// ---------------- main GEMM: C = Acat @ Bcat^T, fused epilogue ----------------
#define MG_BM 128
#define MG_BN 64
#define MG_BK 16
__global__ __launch_bounds__(256) void k_maingemm(const float* __restrict__ p_le,
                                                  const float* __restrict__ p_ls,
                                                  const float* __restrict__ bias) {
    __shared__ float As[MG_BM][MG_BK + 1];
    __shared__ float Bs[MG_BK][MG_BN + 4];
    int bn = blockIdx.x * MG_BN, bm = blockIdx.y * MG_BM;
    int tid = threadIdx.x, tx = tid % 16, ty = tid / 16;
    float acc[8][4], snap[8][4];
    #pragma unroll
    for (int r = 0; r < 8; r++)
        #pragma unroll
        for (int c = 0; c < 4; c++) acc[r][c] = 0.f;

    const int NSTEP = KD / MG_BK;        // 60
    const int PHASE = DN / MG_BK - 1;    // 47 : after this step, first 768 done
    for (int step = 0; step < NSTEP; step++) {
        int k0 = step * MG_BK;
        for (int i = tid; i < MG_BM * MG_BK; i += 256) {
            int kk = i % MG_BK, mm = i / MG_BK;
            As[mm][kk] = g_Acat[(bm + mm) * KD + k0 + kk];
        }
        for (int i = tid; i < MG_BN * MG_BK; i += 256) {
            int kk = i % MG_BK, nn = i / MG_BK, v = bn + nn;
            Bs[kk][nn] = (v < VN) ? g_Bcat[v * KD + k0 + kk] : 0.f;
        }
        __syncthreads();
        #pragma unroll
        for (int kk = 0; kk < MG_BK; kk++) {
            float a[8], b[4];
            #pragma unroll
            for (int r = 0; r < 8; r++) a[r] = As[ty * 8 + r][kk];
            #pragma unroll
            for (int c = 0; c < 4; c++) b[c] = Bs[kk][tx * 4 + c];
            #pragma unroll
            for (int r = 0; r < 8; r++)
                #pragma unroll
                for (int c = 0; c < 4; c++) acc[r][c] += a[r] * b[c];
        }
        __syncthreads();
        if (step == PHASE) {
            #pragma unroll
            for (int r = 0; r < 8; r++)
                #pragma unroll
                for (int c = 0; c < 4; c++) snap[r][c] = acc[r][c];
        }
    }

    float le = *p_le;
    float eps = ((le > 20.f) ? le : log1pf(expf(le))) + 0.001f;
    float inve = 1.f / eps;
    float scale = fminf(expf(*p_ls), 20.f);

    #pragma unroll
    for (int r = 0; r < 8; r++) {
        int gm = bm + ty * 8 + r;
        float aa = g_AA[gm];
        float bi = bias[gm];
        #pragma unroll
        for (int c = 0; c < 4; c++) {
            int v = bn + tx * 4 + c;
            if (v < VN) {
                float ab = acc[r][c];             // s + t  (full 960 dot)
                float s  = snap[r][c];            // s only (first 768)
                float mah = fmaxf(aa + g_BB[v] - 2.f * ab, 0.f);
                g_base[gm * VN + v] = scale * s + bi - 0.3f * mah;
                g_logK[gm * VN + v] = -mah * inve;
            }
        }
    }
}

// ---------------- logsumexp helpers ----------------
__device__ __forceinline__ void lse_combine(float& m, float& s, float m2, float s2) {
    if (s2 == 0.f) return;
    if (m2 > m) { s = s * __expf(m - m2) + s2; m = m2; }
    else        { s += s2 * __expf(m2 - m); }
}

// log_u[k] = -logsumexp_v( logK[k,v] + lv[v] )
__global__ void k_row() {
    int k = blockIdx.x, tid = threadIdx.x;
    const float* row = &g_logK[(size_t)k * VN];
    float m = -INFINITY, s = 0.f;
    for (int v = tid; v < VN; v += 256) {
        float x = row[v] + g_lv[v];
        float nm = fmaxf(m, x);
        s = s * __expf(m - nm) + __expf(x - nm);
        m = nm;
    }
    __shared__ float sm[256], ssum[256];
    sm[tid] = m; ssum[tid] = s; __syncthreads();
    for (int o = 128; o > 0; o >>= 1) {
        if (tid < o) lse_combine(sm[tid], ssum[tid], sm[tid + o], ssum[tid + o]);
        __syncthreads();
    }
    if (tid == 0) g_lu[k] = -(sm[0] + __logf(ssum[0]));
}

// log_v[v] = -logsumexp_k( logK[k,v] + lu[k] )
__global__ void k_col() {
    __shared__ float su[KN];
    int tid = threadIdx.x;
    for (int i = tid; i < KN; i += blockDim.x) su[i] = g_lu[i];
    __syncthreads();
    int v = blockIdx.x * blockDim.x + tid;
    if (v >= VN) return;
    float m = -INFINITY, s = 0.f;
    #pragma unroll 4
    for (int k = 0; k < KN; k++) {
        float x = g_logK[(size_t)k * VN + v] + su[k];
        float nm = fmaxf(m, x);
        s = s * __expf(m - nm) + __expf(x - nm);
        m = nm;
    }
    g_lv[v] = -(m + __logf(s));
}

// ---------------- final softmax ----------------
__global__ void k_finalA() {
    int k = blockIdx.x, tid = threadIdx.x;
    float lu = g_lu[k];
    const float* brow = &g_base[(size_t)k * VN];
    const float* krow = &g_logK[(size_t)k * VN];
    float m = -INFINITY, s = 0.f;
    for (int v = tid; v < VN; v += 256) {
        float x = brow[v] + 0.3f * (krow[v] + lu + g_lv[v]);
        x = fminf(fmaxf(x, -30.f), 30.f);
        float nm = fmaxf(m, x);
        s = s * __expf(m - nm) + __expf(x - nm);
        m = nm;
    }
    __shared__ float sm[256], ssum[256];
    sm[tid] = m; ssum[tid] = s; __syncthreads();
    for (int o = 128; o > 0; o >>= 1) {
        if (tid < o) lse_combine(sm[tid], ssum[tid], sm[tid + o], ssum[tid + o]);
        __syncthreads();
    }
    if (tid == 0) { g_rowm[k] = sm[0]; g_rows[k] = ssum[0]; }
}

__global__ void k_finalB(float* __restrict__ out) {
    int k = blockIdx.y;
    int v = blockIdx.x * blockDim.x + threadIdx.x;
    if (v >= VN) return;
    float lu = g_lu[k];
    float x = g_base[(size_t)k * VN + v] + 0.3f * (g_logK[(size_t)k * VN + v] + lu + g_lv[v]);
    x = fminf(fmaxf(x, -30.f), 30.f);
    out[(size_t)k * VN + v] = __expf(x - g_rowm[k]) / g_rows[k];
}

// ---------------- launch ----------------
extern "C" void kernel_launch(void* const* d_in, const int* in_sizes, int n_in,
                              void* d_out, int out_size) {
    const float* we   = (const float*)d_in[0];   // word_embeds [V, D]
    const float* anch = (const float*)d_in[1];   // concept_anchors [K, D]
    const float* U    = (const float*)d_in[2];   // M_U [D, R]
    const float* p_le = (const float*)d_in[3];   // log_eps scalar
    const float* p_ls = (const float*)d_in[4];   // log_scale scalar
    const float* bias = (const float*)d_in[5];   // topic_bias [K, 1]
    const float* Wp   = (const float*)d_in[6];   // word_proj_w [D, D]
    float* out = (float*)d_out;

    k_init<<<(VN + 255) / 256, 256>>>();
    k_idcheck<<<576, 256>>>(Wp);
    k_anchors<<<KN, 256>>>(anch, U);
    k_wnorm<<<VN, 256>>>(we, Wp);
    k_ubgemm<<<(VN + UB_BM - 1) / UB_BM, 256>>>(U);
    k_bb<<<(VN + 255) / 256, 256>>>();

    dim3 gmain((VN + MG_BN - 1) / MG_BN, KN / MG_BM);
    k_maingemm<<<gmain, 256>>>(p_le, p_ls, bias);

    for (int it = 0; it < 10; it++) {
        k_row<<<KN, 256>>>();
        k_col<<<(VN + 255) / 256, 256>>>();
    }

    k_finalA<<<KN, 256>>>();
    dim3 gf((VN + 255) / 256, KN);
    k_finalB<<<gf, 256>>>(out);
}

// round 3
// speedup vs baseline: 2.1146x; 2.1146x over previous
#include <cuda_runtime.h>
#include <cuda_bf16.h>
#include <math.h>

#define VN 50257
#define VPAD 50304   // 393 * 128
#define KN 512
#define DN 768
#define RN 192
#define KD 960       // DN + RN
#define RS 40        // smem row stride in bf16 (80B, conflict-free for frag loads)

// ---------------- scratch (static device globals; no allocation) ----------------
__device__ __nv_bfloat16 g_Ah[KN * KD];
__device__ __nv_bfloat16 g_Al[KN * KD];
__device__ __nv_bfloat16 g_Bh[(size_t)VPAD * KD];
__device__ __nv_bfloat16 g_Bl[(size_t)VPAD * KD];
__device__ float g_AA[KN];
__device__ float g_BB[VPAD];
__device__ float g_base[(size_t)KN * VN];
__device__ float g_logK[(size_t)KN * VN];
__device__ float g_lu[KN];
__device__ float g_lv[VN];
__device__ float g_rowm[KN];
__device__ float g_rows[KN];
__device__ int   g_idflag;

// ---------------- helpers ----------------
__device__ __forceinline__ void bsplit(float x, __nv_bfloat16& h, __nv_bfloat16& l) {
    h = __float2bfloat16(x);
    l = __float2bfloat16(x - __bfloat162float(h));
}

__device__ __forceinline__ void cp16(void* sm, const void* gp) {
    unsigned sa = (unsigned)__cvta_generic_to_shared(sm);
    asm volatile("cp.async.cg.shared.global [%0], [%1], 16;\n" :: "r"(sa), "l"(gp));
}
__device__ __forceinline__ void cpcommit() { asm volatile("cp.async.commit_group;\n"); }
template<int N> __device__ __forceinline__ void cpwait() {
    asm volatile("cp.async.wait_group %0;\n" :: "n"(N));
}

__device__ __forceinline__ void mma16816(float c[4], const unsigned a[4], const unsigned b[2]) {
    asm volatile(
        "mma.sync.aligned.m16n8k16.row.col.f32.bf16.bf16.f32 "
        "{%0,%1,%2,%3}, {%4,%5,%6,%7}, {%8,%9}, {%0,%1,%2,%3};\n"
        : "+f"(c[0]), "+f"(c[1]), "+f"(c[2]), "+f"(c[3])
        : "r"(a[0]), "r"(a[1]), "r"(a[2]), "r"(a[3]), "r"(b[0]), "r"(b[1]));
}

// ---------------- init: zero log_v, set identity flag ----------------
__global__ void k_init() {
    int i = blockIdx.x * blockDim.x + threadIdx.x;
    if (i < VN) g_lv[i] = 0.f;
    if (i == 0) g_idflag = 1;
}

// ---------------- identity check on word_proj_w ----------------
__global__ void k_idcheck(const float* __restrict__ Wp) {
    int stride = gridDim.x * blockDim.x;
    for (int i = blockIdx.x * blockDim.x + threadIdx.x; i < DN * DN; i += stride) {
        float e = ((i / DN) == (i % DN)) ? 1.f : 0.f;
        if (Wp[i] != e) g_idflag = 0;
    }
}

// ---------------- anchors: normalize, Ua = a@U, AA, write bf16 splits ----------------
__global__ void k_anchors(const float* __restrict__ anch, const float* __restrict__ U) {
    __shared__ float sa[DN];
    __shared__ float sred[256];
    __shared__ float sua[RN];
    int k = blockIdx.x, tid = threadIdx.x;

    float ss = 0.f;
    for (int d = tid; d < DN; d += 256) { float x = anch[k * DN + d]; sa[d] = x; ss += x * x; }
    sred[tid] = ss; __syncthreads();
    for (int o = 128; o > 0; o >>= 1) { if (tid < o) sred[tid] += sred[tid + o]; __syncthreads(); }
    float inv = 1.f / fmaxf(sqrtf(sred[0]), 1e-12f);
    __syncthreads();
    for (int d = tid; d < DN; d += 256) {
        float x = sa[d] * inv; sa[d] = x;
        __nv_bfloat16 h, l; bsplit(x, h, l);
        g_Ah[k * KD + d] = h; g_Al[k * KD + d] = l;
    }
    __syncthreads();
    if (tid < RN) {
        float acc = 0.f;
        for (int d = 0; d < DN; d++) acc += sa[d] * U[d * RN + tid];
        __nv_bfloat16 h, l; bsplit(acc, h, l);
        g_Ah[k * KD + DN + tid] = h; g_Al[k * KD + DN + tid] = l;
        sua[tid] = acc;
    }
    __syncthreads();
    float aa = 0.f;
    for (int r = tid; r < RN; r += 256) aa += sua[r] * sua[r];
    sred[tid] = aa; __syncthreads();
    for (int o = 128; o > 0; o >>= 1) { if (tid < o) sred[tid] += sred[tid + o]; __syncthreads(); }
    if (tid == 0) g_AA[k] = 1.f + sred[0];
}

// ---------------- w_norm: (optional projection) + normalize + bf16 split ----------------
__global__ void k_wnorm(const float* __restrict__ we, const float* __restrict__ Wp) {
    __shared__ float se[DN];
    __shared__ float sw[DN];
    __shared__ float sred[256];
    int v = blockIdx.x, tid = threadIdx.x;

    if (v >= VN) {  // pad rows -> zeros
        for (int d = tid; d < DN; d += 256) {
            g_Bh[(size_t)v * KD + d] = __float2bfloat16(0.f);
            g_Bl[(size_t)v * KD + d] = __float2bfloat16(0.f);
        }
        return;
    }
    int flag = g_idflag;
    for (int d = tid; d < DN; d += 256) se[d] = we[v * DN + d];
    __syncthreads();
    if (flag) {
        for (int d = tid; d < DN; d += 256) sw[d] = se[d];
    } else {
        for (int d = tid; d < DN; d += 256) {
            float acc = 0.f;
            for (int j = 0; j < DN; j++) acc += se[j] * Wp[d * DN + j];
            sw[d] = acc;
        }
    }
    __syncthreads();
    float ss = 0.f;
    for (int d = tid; d < DN; d += 256) { float x = sw[d]; ss += x * x; }
    sred[tid] = ss; __syncthreads();
    for (int o = 128; o > 0; o >>= 1) { if (tid < o) sred[tid] += sred[tid + o]; __syncthreads(); }
    float inv = 1.f / fmaxf(sqrtf(sred[0]), 1e-12f);
    for (int d = tid; d < DN; d += 256) {
        __nv_bfloat16 h, l; bsplit(sw[d] * inv, h, l);
        g_Bh[(size_t)v * KD + d] = h; g_Bl[(size_t)v * KD + d] = l;
    }
}

// ---------------- Ub = w_norm @ U (tensor, split-bf16), fused BB ----------------
// dyn smem: Wh[128*40] Wl[128*40] Uh[192*40] Ul[192*40] (bf16) + sBB[128] (f32) = 51712 B
__global__ __launch_bounds__(256) void k_ubgemm(const float* __restrict__ U) {
    extern __shared__ __nv_bfloat16 dsm[];
    __nv_bfloat16* sWh = dsm;
    __nv_bfloat16* sWl = dsm + 5120;
    __nv_bfloat16* sUh = dsm + 10240;
    __nv_bfloat16* sUl = dsm + 17920;
    float* sBB = (float*)(dsm + 25600);

    int bm = blockIdx.x * 128;
    int tid = threadIdx.x;
    int w = tid >> 5, lane = tid & 31;
    int g = lane >> 2, q = lane & 3;
    int wm = w >> 2, wn = w & 3;          // 2 x 4 warps, warp tile 64 x 48
    if (tid < 128) sBB[tid] = 0.f;

    float acc[4][6][4];
    #pragma unroll
    for (int i = 0; i < 4; i++)
        #pragma unroll
        for (int j = 0; j < 6; j++)
            #pragma unroll
            for (int c = 0; c < 4; c++) acc[i][j][c] = 0.f;

    for (int s = 0; s < 24; s++) {
        int k0 = s * 32;
        __syncthreads();
        for (int c = tid; c < 512; c += 256) {
            int row = c >> 2, ch = c & 3;
            int off = row * RS + ch * 8;
            size_t ga = (size_t)(bm + row) * KD + k0 + ch * 8;
            cp16(sWh + off, g_Bh + ga);
            cp16(sWl + off, g_Bl + ga);
        }
        for (int idx = tid; idx < 32 * RN; idx += 256) {
            int kp = idx / RN, n = idx % RN;
            float u = U[(k0 + kp) * RN + n];
            __nv_bfloat16 h, l; bsplit(u, h, l);
            sUh[n * RS + kp] = h; sUl[n * RS + kp] = l;
        }
        cpcommit(); cpwait<0>();
        __syncthreads();

        #pragma unroll
        for (int kk = 0; kk < 32; kk += 16) {
            unsigned ah[4][4], al[4][4], bh[6][2], bl[6][2];
            #pragma unroll
            for (int i = 0; i < 4; i++) {
                int r0 = (wm * 64 + i * 16 + g) * RS + kk + 2 * q;
                ah[i][0] = *(const unsigned*)(sWh + r0);
                ah[i][1] = *(const unsigned*)(sWh + r0 + 8 * RS);
                ah[i][2] = *(const unsigned*)(sWh + r0 + 8);
                ah[i][3] = *(const unsigned*)(sWh + r0 + 8 * RS + 8);
                al[i][0] = *(const unsigned*)(sWl + r0);
                al[i][1] = *(const unsigned*)(sWl + r0 + 8 * RS);
                al[i][2] = *(const unsigned*)(sWl + r0 + 8);
                al[i][3] = *(const unsigned*)(sWl + r0 + 8 * RS + 8);
            }
            #pragma unroll
            for (int j = 0; j < 6; j++) {
                int n0 = (wn * 48 + j * 8 + g) * RS + kk + 2 * q;
                bh[j][0] = *(const unsigned*)(sUh + n0);
                bh[j][1] = *(const unsigned*)(sUh + n0 + 8);
                bl[j][0] = *(const unsigned*)(sUl + n0);
                bl[j][1] = *(const unsigned*)(sUl + n0 + 8);
            }
            #pragma unroll
            for (int i = 0; i < 4; i++)
                #pragma unroll
                for (int j = 0; j < 6; j++) {
                    mma16816(acc[i][j], ah[i], bh[j]);
                    mma16816(acc[i][j], ah[i], bl[j]);
                    mma16816(acc[i][j], al[i], bh[j]);
                }
        }
    }

    // epilogue: write Ub splits into cols [768,960), accumulate BB
    #pragma unroll
    for (int i = 0; i < 4; i++) {
        int l0 = wm * 64 + i * 16 + g, l1 = l0 + 8;
        size_t m0 = (size_t)(bm + l0) * KD + DN;
        size_t m1 = (size_t)(bm + l1) * KD + DN;
        float p0 = 0.f, p1 = 0.f;
        #pragma unroll
        for (int j = 0; j < 6; j++) {
            int n0 = wn * 48 + j * 8 + 2 * q;
            float x00 = acc[i][j][0], x01 = acc[i][j][1];
            float x10 = acc[i][j][2], x11 = acc[i][j][3];
            p0 += x00 * x00 + x01 * x01;
            p1 += x10 * x10 + x11 * x11;
            __nv_bfloat16 h, l;
            bsplit(x00, h, l); g_Bh[m0 + n0] = h;     g_Bl[m0 + n0] = l;
            bsplit(x01, h, l); g_Bh[m0 + n0 + 1] = h; g_Bl[m0 + n0 + 1] = l;
            bsplit(x10, h, l); g_Bh[m1 + n0] = h;     g_Bl[m1 + n0] = l;
            bsplit(x11, h, l); g_Bh[m1 + n0 + 1] = h; g_Bl[m1 + n0 + 1] = l;
        }
        p0 += __shfl_xor_sync(0xffffffffu, p0, 1); p0 += __shfl_xor_sync(0xffffffffu, p0, 2);
        p1 += __shfl_xor_sync(0xffffffffu, p1, 1); p1 += __shfl_xor_sync(0xffffffffu, p1, 2);
        if (q == 0) { atomicAdd(&sBB[l0], p0); atomicAdd(&sBB[l1], p1); }
    }
    __syncthreads();
    if (tid < 128) g_BB[bm + tid] = 1.f + sBB[tid];
}

// ---------------- main GEMM (tensor, split-bf16, dual acc) + fused epilogue ----------------
__device__ __forceinline__ void mg_compute(const __nv_bfloat16* sb, int wm, int wn,
                                           int g, int q, float acc[4][4][4]) {
    const __nv_bfloat16* sAh = sb;
    const __nv_bfloat16* sAl = sb + 5120;
    const __nv_bfloat16* sBh = sb + 10240;
    const __nv_bfloat16* sBl = sb + 15360;
    #pragma unroll
    for (int kk = 0; kk < 32; kk += 16) {
        unsigned ah[4][4], al[4][4], bh[4][2], bl[4][2];
        #pragma unroll
        for (int i = 0; i < 4; i++) {
            int r0 = (wm * 64 + i * 16 + g) * RS + kk + 2 * q;
            ah[i][0] = *(const unsigned*)(sAh + r0);
            ah[i][1] = *(const unsigned*)(sAh + r0 + 8 * RS);
            ah[i][2] = *(const unsigned*)(sAh + r0 + 8);
            ah[i][3] = *(const unsigned*)(sAh + r0 + 8 * RS + 8);
            al[i][0] = *(const unsigned*)(sAl + r0);
            al[i][1] = *(const unsigned*)(sAl + r0 + 8 * RS);
            al[i][2] = *(const unsigned*)(sAl + r0 + 8);
            al[i][3] = *(const unsigned*)(sAl + r0 + 8 * RS + 8);
        }
        #pragma unroll
        for (int j = 0; j < 4; j++) {
            int n0 = (wn * 32 + j * 8 + g) * RS + kk + 2 * q;
            bh[j][0] = *(const unsigned*)(sBh + n0);
            bh[j][1] = *(const unsigned*)(sBh + n0 + 8);
            bl[j][0] = *(const unsigned*)(sBl + n0);
            bl[j][1] = *(const unsigned*)(sBl + n0 + 8);
        }
        #pragma unroll
        for (int i = 0; i < 4; i++)
            #pragma unroll
            for (int j = 0; j < 4; j++) {
                mma16816(acc[i][j], ah[i], bh[j]);
                mma16816(acc[i][j], ah[i], bl[j]);
                mma16816(acc[i][j], al[i], bh[j]);
            }
    }
}

// dyn smem: 2 stages * (Ah,Al,Bh,Bl each 128*40 bf16) = 81920 B
__global__ __launch_bounds__(256) void k_maingemm(const float* __restrict__ p_le,
                                                  const float* __restrict__ p_ls,
                                                  const float* __restrict__ bias) {
    extern __shared__ __nv_bfloat16 dsm[];
    int bm = blockIdx.y * 128, bn = blockIdx.x * 128;
    int tid = threadIdx.x;
    int w = tid >> 5, lane = tid & 31;
    int g = lane >> 2, q = lane & 3;
    int wm = w >> 2, wn = w & 3;          // 2 x 4 warps, warp tile 64 x 32

    float accS[4][4][4], accT[4][4][4];
    #pragma unroll
    for (int i = 0; i < 4; i++)
        #pragma unroll
        for (int j = 0; j < 4; j++)
            #pragma unroll
            for (int c = 0; c < 4; c++) { accS[i][j][c] = 0.f; accT[i][j][c] = 0.f; }

    // stage loader
    auto load_stage = [&](int s, int buf) {
        __nv_bfloat16* base = dsm + buf * 20480;
        int k0 = s * 32;
        for (int c = tid; c < 512; c += 256) {
            int row = c >> 2, ch = c & 3;
            int off = row * RS + ch * 8;
            size_t ga = (size_t)(bm + row) * KD + k0 + ch * 8;
            size_t gb = (size_t)(bn + row) * KD + k0 + ch * 8;
            cp16(base + off,         g_Ah + ga);
            cp16(base + 5120 + off,  g_Al + ga);
            cp16(base + 10240 + off, g_Bh + gb);
            cp16(base + 15360 + off, g_Bl + gb);
        }
    };

    load_stage(0, 0); cpcommit();
    for (int s = 0; s < 30; s++) {
        int buf = s & 1;
        if (s < 29) { load_stage(s + 1, buf ^ 1); cpcommit(); cpwait<1>(); }
        else        { cpwait<0>(); }
        __syncthreads();
        if (s < 24) mg_compute(dsm + buf * 20480, wm, wn, g, q, accS);
        else        mg_compute(dsm + buf * 20480, wm, wn, g, q, accT);
        __syncthreads();
    }

    float le = *p_le;
    float eps = ((le > 20.f) ? le : log1pf(expf(le))) + 0.001f;
    float inve = 1.f / eps;
    float scale = fminf(expf(*p_ls), 20.f);

    #pragma unroll
    for (int i = 0; i < 4; i++) {
        int m0 = bm + wm * 64 + i * 16 + g;
        int m1 = m0 + 8;
        float aa0 = g_AA[m0], aa1 = g_AA[m1];
        float bi0 = bias[m0], bi1 = bias[m1];
        #pragma unroll
        for (int j = 0; j < 4; j++) {
            int v0 = bn + wn * 32 + j * 8 + 2 * q;
            int v1 = v0 + 1;
            if (v0 < VN) {
                float bb = g_BB[v0];
                float sv = accS[i][j][0], ab = sv + accT[i][j][0];
                float mah = fmaxf(aa0 + bb - 2.f * ab, 0.f);
                g_base[(size_t)m0 * VN + v0] = scale * sv + bi0 - 0.3f * mah;
                g_logK[(size_t)m0 * VN + v0] = -mah * inve;
                sv = accS[i][j][2]; ab = sv + accT[i][j][2];
                mah = fmaxf(aa1 + bb - 2.f * ab, 0.f);
                g_base[(size_t)m1 * VN + v0] = scale * sv + bi1 - 0.3f * mah;
                g_logK[(size_t)m1 * VN + v0] = -mah * inve;
            }
            if (v1 < VN) {
                float bb = g_BB[v1];
                float sv = accS[i][j][1], ab = sv + accT[i][j][1];
                float mah = fmaxf(aa0 + bb - 2.f * ab, 0.f);
                g_base[(size_t)m0 * VN + v1] = scale * sv + bi0 - 0.3f * mah;
                g_logK[(size_t)m0 * VN + v1] = -mah * inve;
                sv = accS[i][j][3]; ab = sv + accT[i][j][3];
                mah = fmaxf(aa1 + bb - 2.f * ab, 0.f);
                g_base[(size_t)m1 * VN + v1] = scale * sv + bi1 - 0.3f * mah;
                g_logK[(size_t)m1 * VN + v1] = -mah * inve;
            }
        }
    }
}

// ---------------- logsumexp helpers ----------------
__device__ __forceinline__ void lse_combine(float& m, float& s, float m2, float s2) {
    if (s2 == 0.f) return;
    if (m2 > m) { s = s * __expf(m - m2) + s2; m = m2; }
    else        { s += s2 * __expf(m2 - m); }
}

__global__ void k_row() {
    int k = blockIdx.x, tid = threadIdx.x;
    const float* row = &g_logK[(size_t)k * VN];
    float m = -INFINITY, s = 0.f;
    for (int v = tid; v < VN; v += 256) {
        float x = row[v] + g_lv[v];
        float nm = fmaxf(m, x);
        s = s * __expf(m - nm) + __expf(x - nm);
        m = nm;
    }
    __shared__ float sm[256], ssum[256];
    sm[tid] = m; ssum[tid] = s; __syncthreads();
    for (int o = 128; o > 0; o >>= 1) {
        if (tid < o) lse_combine(sm[tid], ssum[tid], sm[tid + o], ssum[tid + o]);
        __syncthreads();
    }
    if (tid == 0) g_lu[k] = -(sm[0] + __logf(ssum[0]));
}

__global__ void k_col() {
    __shared__ float su[KN];
    int tid = threadIdx.x;
    for (int i = tid; i < KN; i += blockDim.x) su[i] = g_lu[i];
    __syncthreads();
    int v = blockIdx.x * blockDim.x + tid;
    if (v >= VN) return;
    float m = -INFINITY, s = 0.f;
    #pragma unroll 4
    for (int k = 0; k < KN; k++) {
        float x = g_logK[(size_t)k * VN + v] + su[k];
        float nm = fmaxf(m, x);
        s = s * __expf(m - nm) + __expf(x - nm);
        m = nm;
    }
    g_lv[v] = -(m + __logf(s));
}

// ---------------- final softmax ----------------
__global__ void k_finalA() {
    int k = blockIdx.x, tid = threadIdx.x;
    float lu = g_lu[k];
    const float* brow = &g_base[(size_t)k * VN];
    const float* krow = &g_logK[(size_t)k * VN];
    float m = -INFINITY, s = 0.f;
    for (int v = tid; v < VN; v += 256) {
        float x = brow[v] + 0.3f * (krow[v] + lu + g_lv[v]);
        x = fminf(fmaxf(x, -30.f), 30.f);
        float nm = fmaxf(m, x);
        s = s * __expf(m - nm) + __expf(x - nm);
        m = nm;
    }
    __shared__ float sm[256], ssum[256];
    sm[tid] = m; ssum[tid] = s; __syncthreads();
    for (int o = 128; o > 0; o >>= 1) {
        if (tid < o) lse_combine(sm[tid], ssum[tid], sm[tid + o], ssum[tid + o]);
        __syncthreads();
    }
    if (tid == 0) { g_rowm[k] = sm[0]; g_rows[k] = ssum[0]; }
}

__global__ void k_finalB(float* __restrict__ out) {
    int k = blockIdx.y;
    int v = blockIdx.x * blockDim.x + threadIdx.x;
    if (v >= VN) return;
    float lu = g_lu[k];
    float x = g_base[(size_t)k * VN + v] + 0.3f * (g_logK[(size_t)k * VN + v] + lu + g_lv[v]);
    x = fminf(fmaxf(x, -30.f), 30.f);
    out[(size_t)k * VN + v] = __expf(x - g_rowm[k]) / g_rows[k];
}

// ---------------- launch ----------------
extern "C" void kernel_launch(void* const* d_in, const int* in_sizes, int n_in,
                              void* d_out, int out_size) {
    const float* we   = (const float*)d_in[0];
    const float* anch = (const float*)d_in[1];
    const float* U    = (const float*)d_in[2];
    const float* p_le = (const float*)d_in[3];
    const float* p_ls = (const float*)d_in[4];
    const float* bias = (const float*)d_in[5];
    const float* Wp   = (const float*)d_in[6];
    float* out = (float*)d_out;

    cudaFuncSetAttribute(k_ubgemm,   cudaFuncAttributeMaxDynamicSharedMemorySize, 51712);
    cudaFuncSetAttribute(k_maingemm, cudaFuncAttributeMaxDynamicSharedMemorySize, 81920);

    k_init<<<(VN + 255) / 256, 256>>>();
    k_idcheck<<<576, 256>>>(Wp);
    k_anchors<<<KN, 256>>>(anch, U);
    k_wnorm<<<VPAD, 256>>>(we, Wp);
    k_ubgemm<<<VPAD / 128, 256, 51712>>>(U);

    dim3 gmain(VPAD / 128, KN / 128);
    k_maingemm<<<gmain, 256, 81920>>>(p_le, p_ls, bias);

    for (int it = 0; it < 10; it++) {
        k_row<<<KN, 256>>>();
        k_col<<<(VN + 255) / 256, 256>>>();
    }

    k_finalA<<<KN, 256>>>();
    dim3 gf((VN + 255) / 256, KN);
    k_finalB<<<gf, 256>>>(out);
}

// round 4
// speedup vs baseline: 3.1854x; 1.5064x over previous
#include <cuda_runtime.h>
#include <cuda_bf16.h>
#include <math.h>

#define VN 50257
#define VPAD 50304   // 393 * 128
#define KN 512
#define DN 768
#define RN 192
#define KD 960       // DN + RN
#define RS 40        // smem row stride in bf16 (80B, conflict-free for ldmatrix)

// ---------------- scratch (static device globals; no allocation) ----------------
__device__ __nv_bfloat16 g_Ah[KN * KD];
__device__ __nv_bfloat16 g_Al[KN * KD];
__device__ __nv_bfloat16 g_Bh[(size_t)VPAD * KD];
__device__ __nv_bfloat16 g_Bl[(size_t)VPAD * KD];
__device__ float g_AA[KN];
__device__ float g_BB[VPAD];
__device__ float g_base[(size_t)KN * VPAD];   // scale*s + bias - 0.3*mahal
__device__ float g_K[(size_t)KN * VPAD];      // exp(-mahal/eps); 0 in pad cols
__device__ float g_u[KN];                      // linear sinkhorn u
__device__ float g_v[VPAD];                    // linear sinkhorn v (pads = 1)
__device__ float g_lvl[VPAD];                  // log(v)
__device__ float g_rinv[KN];                   // 1/softmax row sum
__device__ int   g_idflag;

// ---------------- helpers ----------------
__device__ __forceinline__ void bsplit(float x, __nv_bfloat16& h, __nv_bfloat16& l) {
    h = __float2bfloat16(x);
    l = __float2bfloat16(x - __bfloat162float(h));
}

__device__ __forceinline__ void cp16(void* sm, const void* gp) {
    unsigned sa = (unsigned)__cvta_generic_to_shared(sm);
    asm volatile("cp.async.cg.shared.global [%0], [%1], 16;\n" :: "r"(sa), "l"(gp));
}
__device__ __forceinline__ void cpcommit() { asm volatile("cp.async.commit_group;\n"); }
template<int N> __device__ __forceinline__ void cpwait() {
    asm volatile("cp.async.wait_group %0;\n" :: "n"(N));
}

__device__ __forceinline__ void mma16816(float c[4], const unsigned a[4], const unsigned b[2]) {
    asm volatile(
        "mma.sync.aligned.m16n8k16.row.col.f32.bf16.bf16.f32 "
        "{%0,%1,%2,%3}, {%4,%5,%6,%7}, {%8,%9}, {%0,%1,%2,%3};\n"
        : "+f"(c[0]), "+f"(c[1]), "+f"(c[2]), "+f"(c[3])
        : "r"(a[0]), "r"(a[1]), "r"(a[2]), "r"(a[3]), "r"(b[0]), "r"(b[1]));
}

__device__ __forceinline__ void ldsm4(unsigned r[4], const __nv_bfloat16* p) {
    unsigned a = (unsigned)__cvta_generic_to_shared(p);
    asm volatile("ldmatrix.sync.aligned.m8n8.x4.shared.b16 {%0,%1,%2,%3}, [%4];\n"
                 : "=r"(r[0]), "=r"(r[1]), "=r"(r[2]), "=r"(r[3]) : "r"(a));
}

// ---------------- init ----------------
__global__ void k_init() {
    int i = blockIdx.x * blockDim.x + threadIdx.x;
    if (i < VPAD) g_v[i] = 1.f;
    if (i == 0) g_idflag = 1;
}

__global__ void k_idcheck(const float* __restrict__ Wp) {
    int stride = gridDim.x * blockDim.x;
    for (int i = blockIdx.x * blockDim.x + threadIdx.x; i < DN * DN; i += stride) {
        float e = ((i / DN) == (i % DN)) ? 1.f : 0.f;
        if (Wp[i] != e) g_idflag = 0;
    }
}

// ---------------- anchors: normalize, Ua = a@U, AA, write bf16 splits ----------------
__global__ void k_anchors(const float* __restrict__ anch, const float* __restrict__ U) {
    __shared__ float sa[DN];
    __shared__ float sred[256];
    __shared__ float sua[RN];
    int k = blockIdx.x, tid = threadIdx.x;

    float ss = 0.f;
    for (int d = tid; d < DN; d += 256) { float x = anch[k * DN + d]; sa[d] = x; ss += x * x; }
    sred[tid] = ss; __syncthreads();
    for (int o = 128; o > 0; o >>= 1) { if (tid < o) sred[tid] += sred[tid + o]; __syncthreads(); }
    float inv = 1.f / fmaxf(sqrtf(sred[0]), 1e-12f);
    __syncthreads();
    for (int d = tid; d < DN; d += 256) {
        float x = sa[d] * inv; sa[d] = x;
        __nv_bfloat16 h, l; bsplit(x, h, l);
        g_Ah[k * KD + d] = h; g_Al[k * KD + d] = l;
    }
    __syncthreads();
    if (tid < RN) {
        float acc = 0.f;
        for (int d = 0; d < DN; d++) acc += sa[d] * U[d * RN + tid];
        __nv_bfloat16 h, l; bsplit(acc, h, l);
        g_Ah[k * KD + DN + tid] = h; g_Al[k * KD + DN + tid] = l;
        sua[tid] = acc;
    }
    __syncthreads();
    float aa = 0.f;
    for (int r = tid; r < RN; r += 256) aa += sua[r] * sua[r];
    sred[tid] = aa; __syncthreads();
    for (int o = 128; o > 0; o >>= 1) { if (tid < o) sred[tid] += sred[tid + o]; __syncthreads(); }
    if (tid == 0) g_AA[k] = 1.f + sred[0];
}

// ---------------- w_norm: warp-per-row, float4, bf16 splits ----------------
__global__ __launch_bounds__(256) void k_wnorm(const float* __restrict__ we,
                                               const float* __restrict__ Wp) {
    int warp = threadIdx.x >> 5, lane = threadIdx.x & 31;
    int v = blockIdx.x * 8 + warp;
    if (v >= VPAD) return;
    size_t gb = (size_t)v * KD;
    if (v >= VN) {
        #pragma unroll
        for (int c = 0; c < 6; c++) {
            int d = c * 128 + lane * 4;
            *(uint2*)&g_Bh[gb + d] = make_uint2(0u, 0u);
            *(uint2*)&g_Bl[gb + d] = make_uint2(0u, 0u);
        }
        return;
    }
    int flag = g_idflag;
    float4 x[6];
    if (flag) {
        #pragma unroll
        for (int c = 0; c < 6; c++)
            x[c] = *(const float4*)&we[(size_t)v * DN + c * 128 + lane * 4];
    } else {
        // slow fallback (unused for this dataset)
        for (int c = 0; c < 6; c++) {
            float r[4];
            for (int u2 = 0; u2 < 4; u2++) {
                int d = c * 128 + lane * 4 + u2;
                float acc = 0.f;
                for (int j = 0; j < DN; j++) acc += we[(size_t)v * DN + j] * Wp[d * DN + j];
                r[u2] = acc;
            }
            x[c] = make_float4(r[0], r[1], r[2], r[3]);
        }
    }
    float ss = 0.f;
    #pragma unroll
    for (int c = 0; c < 6; c++)
        ss += x[c].x * x[c].x + x[c].y * x[c].y + x[c].z * x[c].z + x[c].w * x[c].w;
    #pragma unroll
    for (int o = 16; o > 0; o >>= 1) ss += __shfl_xor_sync(0xffffffffu, ss, o);
    float inv = 1.f / fmaxf(sqrtf(ss), 1e-12f);
    #pragma unroll
    for (int c = 0; c < 6; c++) {
        int d = c * 128 + lane * 4;
        float vl[4] = {x[c].x * inv, x[c].y * inv, x[c].z * inv, x[c].w * inv};
        __nv_bfloat16 h[4], l[4];
        #pragma unroll
        for (int t = 0; t < 4; t++) bsplit(vl[t], h[t], l[t]);
        *(__nv_bfloat162*)&g_Bh[gb + d]     = __nv_bfloat162(h[0], h[1]);
        *(__nv_bfloat162*)&g_Bh[gb + d + 2] = __nv_bfloat162(h[2], h[3]);
        *(__nv_bfloat162*)&g_Bl[gb + d]     = __nv_bfloat162(l[0], l[1]);
        *(__nv_bfloat162*)&g_Bl[gb + d + 2] = __nv_bfloat162(l[2], l[3]);
    }
}

// ---------------- Ub = w_norm @ U (tensor, split-bf16, ldmatrix), fused BB ----------------
__global__ __launch_bounds__(256) void k_ubgemm(const float* __restrict__ U) {
    extern __shared__ __nv_bfloat16 dsm[];
    __nv_bfloat16* sWh = dsm;
    __nv_bfloat16* sWl = dsm + 5120;
    __nv_bfloat16* sUh = dsm + 10240;
    __nv_bfloat16* sUl = dsm + 17920;
    float* sBB = (float*)(dsm + 25600);

    int bm = blockIdx.x * 128;
    int tid = threadIdx.x;
    int w = tid >> 5, lane = tid & 31;
    int g = lane >> 2, q = lane & 3;
    int wm = w >> 2, wn = w & 3;          // 2 x 4 warps, warp tile 64 x 48
    int mi = lane >> 3, lr = lane & 7;
    int aoff = (wm * 64 + (mi & 1) * 8 + lr) * RS + (mi >> 1) * 8;
    int boff = (wn * 48 + (mi >> 1) * 8 + lr) * RS + (mi & 1) * 8;
    if (tid < 128) sBB[tid] = 0.f;

    float acc[4][6][4];
    #pragma unroll
    for (int i = 0; i < 4; i++)
        #pragma unroll
        for (int j = 0; j < 6; j++)
            #pragma unroll
            for (int c = 0; c < 4; c++) acc[i][j][c] = 0.f;

    for (int s = 0; s < 24; s++) {
        int k0 = s * 32;
        __syncthreads();
        for (int c = tid; c < 512; c += 256) {
            int row = c >> 2, ch = c & 3;
            int off = row * RS + ch * 8;
            size_t ga = (size_t)(bm + row) * KD + k0 + ch * 8;
            cp16(sWh + off, g_Bh + ga);
            cp16(sWl + off, g_Bl + ga);
        }
        for (int idx = tid; idx < 32 * RN; idx += 256) {
            int kp = idx / RN, n = idx % RN;
            float u = U[(k0 + kp) * RN + n];
            __nv_bfloat16 h, l; bsplit(u, h, l);
            sUh[n * RS + kp] = h; sUl[n * RS + kp] = l;
        }
        cpcommit(); cpwait<0>();
        __syncthreads();

        #pragma unroll
        for (int kk = 0; kk < 32; kk += 16) {
            unsigned ah[4][4], al[4][4], bh[6][2], bl[6][2];
            #pragma unroll
            for (int i = 0; i < 4; i++) {
                ldsm4(ah[i], sWh + aoff + i * 16 * RS + kk);
                ldsm4(al[i], sWl + aoff + i * 16 * RS + kk);
            }
            #pragma unroll
            for (int jp = 0; jp < 3; jp++) {
                unsigned t[4];
                ldsm4(t, sUh + boff + jp * 16 * RS + kk);
                bh[2*jp][0] = t[0]; bh[2*jp][1] = t[1];
                bh[2*jp+1][0] = t[2]; bh[2*jp+1][1] = t[3];
                ldsm4(t, sUl + boff + jp * 16 * RS + kk);
                bl[2*jp][0] = t[0]; bl[2*jp][1] = t[1];
                bl[2*jp+1][0] = t[2]; bl[2*jp+1][1] = t[3];
            }
            #pragma unroll
            for (int i = 0; i < 4; i++)
                #pragma unroll
                for (int j = 0; j < 6; j++) {
                    mma16816(acc[i][j], ah[i], bh[j]);
                    mma16816(acc[i][j], ah[i], bl[j]);
                    mma16816(acc[i][j], al[i], bh[j]);
                }
        }
    }

    #pragma unroll
    for (int i = 0; i < 4; i++) {
        int l0 = wm * 64 + i * 16 + g, l1 = l0 + 8;
        size_t m0 = (size_t)(bm + l0) * KD + DN;
        size_t m1 = (size_t)(bm + l1) * KD + DN;
        float p0 = 0.f, p1 = 0.f;
        #pragma unroll
        for (int j = 0; j < 6; j++) {
            int n0 = wn * 48 + j * 8 + 2 * q;
            float x00 = acc[i][j][0], x01 = acc[i][j][1];
            float x10 = acc[i][j][2], x11 = acc[i][j][3];
            p0 += x00 * x00 + x01 * x01;
            p1 += x10 * x10 + x11 * x11;
            __nv_bfloat16 h, l;
            bsplit(x00, h, l); g_Bh[m0 + n0] = h;     g_Bl[m0 + n0] = l;
            bsplit(x01, h, l); g_Bh[m0 + n0 + 1] = h; g_Bl[m0 + n0 + 1] = l;
            bsplit(x10, h, l); g_Bh[m1 + n0] = h;     g_Bl[m1 + n0] = l;
            bsplit(x11, h, l); g_Bh[m1 + n0 + 1] = h; g_Bl[m1 + n0 + 1] = l;
        }
        p0 += __shfl_xor_sync(0xffffffffu, p0, 1); p0 += __shfl_xor_sync(0xffffffffu, p0, 2);
        p1 += __shfl_xor_sync(0xffffffffu, p1, 1); p1 += __shfl_xor_sync(0xffffffffu, p1, 2);
        if (q == 0) { atomicAdd(&sBB[l0], p0); atomicAdd(&sBB[l1], p1); }
    }
    __syncthreads();
    if (tid < 128) g_BB[bm + tid] = 1.f + sBB[tid];
}

// ---------------- main GEMM (tensor, split-bf16, ldmatrix, dual acc) ----------------
__device__ __forceinline__ void mg_compute(const __nv_bfloat16* sb, int aoff, int boff,
                                           float acc[4][4][4]) {
    const __nv_bfloat16* sAh = sb;
    const __nv_bfloat16* sAl = sb + 5120;
    const __nv_bfloat16* sBh = sb + 10240;
    const __nv_bfloat16* sBl = sb + 15360;
    #pragma unroll
    for (int kk = 0; kk < 32; kk += 16) {
        unsigned ah[4][4], al[4][4], bh[4][2], bl[4][2];
        #pragma unroll
        for (int i = 0; i < 4; i++) {
            ldsm4(ah[i], sAh + aoff + i * 16 * RS + kk);
            ldsm4(al[i], sAl + aoff + i * 16 * RS + kk);
        }
        #pragma unroll
        for (int jp = 0; jp < 2; jp++) {
            unsigned t[4];
            ldsm4(t, sBh + boff + jp * 16 * RS + kk);
            bh[2*jp][0] = t[0]; bh[2*jp][1] = t[1];
            bh[2*jp+1][0] = t[2]; bh[2*jp+1][1] = t[3];
            ldsm4(t, sBl + boff + jp * 16 * RS + kk);
            bl[2*jp][0] = t[0]; bl[2*jp][1] = t[1];
            bl[2*jp+1][0] = t[2]; bl[2*jp+1][1] = t[3];
        }
        #pragma unroll
        for (int i = 0; i < 4; i++)
            #pragma unroll
            for (int j = 0; j < 4; j++) {
                mma16816(acc[i][j], ah[i], bh[j]);
                mma16816(acc[i][j], ah[i], bl[j]);
                mma16816(acc[i][j], al[i], bh[j]);
            }
    }
}

// grid: (KN/128, VPAD/128); dyn smem 81920 B
__global__ __launch_bounds__(256) void k_maingemm(const float* __restrict__ p_le,
                                                  const float* __restrict__ p_ls,
                                                  const float* __restrict__ bias) {
    extern __shared__ __nv_bfloat16 dsm[];
    int bm = blockIdx.x * 128, bn = blockIdx.y * 128;
    int tid = threadIdx.x;
    int w = tid >> 5, lane = tid & 31;
    int g = lane >> 2, q = lane & 3;
    int wm = w >> 2, wn = w & 3;          // 2 x 4 warps, warp tile 64 x 32
    int mi = lane >> 3, lr = lane & 7;
    int aoff = (wm * 64 + (mi & 1) * 8 + lr) * RS + (mi >> 1) * 8;
    int boff = (wn * 32 + (mi >> 1) * 8 + lr) * RS + (mi & 1) * 8;

    float accS[4][4][4], accT[4][4][4];
    #pragma unroll
    for (int i = 0; i < 4; i++)
        #pragma unroll
        for (int j = 0; j < 4; j++)
            #pragma unroll
            for (int c = 0; c < 4; c++) { accS[i][j][c] = 0.f; accT[i][j][c] = 0.f; }

    auto load_stage = [&](int s, int buf) {
        __nv_bfloat16* base = dsm + buf * 20480;
        int k0 = s * 32;
        for (int c = tid; c < 512; c += 256) {
            int row = c >> 2, ch = c & 3;
            int off = row * RS + ch * 8;
            size_t ga = (size_t)(bm + row) * KD + k0 + ch * 8;
            size_t gb = (size_t)(bn + row) * KD + k0 + ch * 8;
            cp16(base + off,         g_Ah + ga);
            cp16(base + 5120 + off,  g_Al + ga);
            cp16(base + 10240 + off, g_Bh + gb);
            cp16(base + 15360 + off, g_Bl + gb);
        }
    };

    load_stage(0, 0); cpcommit();
    for (int s = 0; s < 30; s++) {
        int buf = s & 1;
        if (s < 29) { load_stage(s + 1, buf ^ 1); cpcommit(); cpwait<1>(); }
        else        { cpwait<0>(); }
        __syncthreads();
        if (s < 24) mg_compute(dsm + buf * 20480, aoff, boff, accS);
        else        mg_compute(dsm + buf * 20480, aoff, boff, accT);
        __syncthreads();
    }

    float le = *p_le;
    float eps = ((le > 20.f) ? le : log1pf(expf(le))) + 0.001f;
    float inve = 1.f / eps;
    float scale = fminf(expf(*p_ls), 20.f);

    #pragma unroll
    for (int i = 0; i < 4; i++) {
        int m0 = bm + wm * 64 + i * 16 + g;
        int m1 = m0 + 8;
        float aa0 = g_AA[m0], aa1 = g_AA[m1];
        float bi0 = bias[m0], bi1 = bias[m1];
        #pragma unroll
        for (int j = 0; j < 4; j++) {
            #pragma unroll
            for (int c = 0; c < 2; c++) {
                int v = bn + wn * 32 + j * 8 + 2 * q + c;
                float bb = g_BB[v];
                int inr = (v < VN);
                float sv = accS[i][j][c], ab = sv + accT[i][j][c];
                float mah = fmaxf(aa0 + bb - 2.f * ab, 0.f);
                g_base[(size_t)m0 * VPAD + v] = scale * sv + bi0 - 0.3f * mah;
                g_K[(size_t)m0 * VPAD + v] = inr ? __expf(-mah * inve) : 0.f;
                sv = accS[i][j][c + 2]; ab = sv + accT[i][j][c + 2];
                mah = fmaxf(aa1 + bb - 2.f * ab, 0.f);
                g_base[(size_t)m1 * VPAD + v] = scale * sv + bi1 - 0.3f * mah;
                g_K[(size_t)m1 * VPAD + v] = inr ? __expf(-mah * inve) : 0.f;
            }
        }
    }
}

// ---------------- linear-domain Sinkhorn ----------------
// u[k] = 1 / sum_v K[k,v] * v[v]
__global__ __launch_bounds__(256) void k_rowlin() {
    int k = blockIdx.x, tid = threadIdx.x;
    const float4* K4 = (const float4*)&g_K[(size_t)k * VPAD];
    const float4* V4 = (const float4*)g_v;
    float s = 0.f;
    for (int i = tid; i < VPAD / 4; i += 256) {
        float4 a = K4[i], b = V4[i];
        s += a.x * b.x + a.y * b.y + a.z * b.z + a.w * b.w;
    }
    __shared__ float sr[256];
    sr[tid] = s; __syncthreads();
    for (int o = 128; o > 0; o >>= 1) { if (tid < o) sr[tid] += sr[tid + o]; __syncthreads(); }
    if (tid == 0) g_u[k] = 1.f / sr[0];
}

// v[v] = 1 / sum_k K[k,v] * u[k]
__global__ __launch_bounds__(256) void k_collin() {
    __shared__ float su[KN];
    int tid = threadIdx.x;
    for (int i = tid; i < KN; i += 256) su[i] = g_u[i];
    __syncthreads();
    int v = blockIdx.x * 256 + tid;
    if (v >= VN) return;
    const float* col = g_K + v;
    float s0 = 0.f, s1 = 0.f, s2 = 0.f, s3 = 0.f;
    #pragma unroll 4
    for (int k = 0; k < KN; k += 4) {
        s0 += col[(size_t)(k    ) * VPAD] * su[k];
        s1 += col[(size_t)(k + 1) * VPAD] * su[k + 1];
        s2 += col[(size_t)(k + 2) * VPAD] * su[k + 2];
        s3 += col[(size_t)(k + 3) * VPAD] * su[k + 3];
    }
    g_v[v] = 1.f / (s0 + s1 + s2 + s3);
}

__global__ void k_lvlog() {
    int v = blockIdx.x * blockDim.x + threadIdx.x;
    if (v < VN) g_lvl[v] = __logf(g_v[v]);
}

// ---------------- final softmax (fixed max = 30 after clip) ----------------
__global__ __launch_bounds__(256) void k_finalA() {
    int k = blockIdx.x, tid = threadIdx.x;
    float lul = __logf(g_u[k]);
    const float* brow = g_base + (size_t)k * VPAD;
    const float* krow = g_K + (size_t)k * VPAD;
    float s = 0.f;
    for (int i = tid; i < 12564; i += 256) {
        float4 b4 = *(const float4*)&brow[i * 4];
        float4 k4 = *(const float4*)&krow[i * 4];
        float4 l4 = *(const float4*)&g_lvl[i * 4];
        float x;
        x = b4.x + 0.3f * (__logf(k4.x) + lul + l4.x); x = fminf(fmaxf(x, -30.f), 30.f); s += __expf(x - 30.f);
        x = b4.y + 0.3f * (__logf(k4.y) + lul + l4.y); x = fminf(fmaxf(x, -30.f), 30.f); s += __expf(x - 30.f);
        x = b4.z + 0.3f * (__logf(k4.z) + lul + l4.z); x = fminf(fmaxf(x, -30.f), 30.f); s += __expf(x - 30.f);
        x = b4.w + 0.3f * (__logf(k4.w) + lul + l4.w); x = fminf(fmaxf(x, -30.f), 30.f); s += __expf(x - 30.f);
    }
    if (tid == 0) {  // tail element v = 50256
        float x = brow[50256] + 0.3f * (__logf(krow[50256]) + lul + g_lvl[50256]);
        x = fminf(fmaxf(x, -30.f), 30.f); s += __expf(x - 30.f);
    }
    __shared__ float sr[256];
    sr[tid] = s; __syncthreads();
    for (int o = 128; o > 0; o >>= 1) { if (tid < o) sr[tid] += sr[tid + o]; __syncthreads(); }
    if (tid == 0) g_rinv[k] = 1.f / sr[0];
}

__global__ __launch_bounds__(256) void k_finalB(float* __restrict__ out) {
    int k = blockIdx.y;
    int v = blockIdx.x * 256 + threadIdx.x;
    if (v >= VN) return;
    float lul = __logf(g_u[k]);
    float x = g_base[(size_t)k * VPAD + v]
            + 0.3f * (__logf(g_K[(size_t)k * VPAD + v]) + lul + g_lvl[v]);
    x = fminf(fmaxf(x, -30.f), 30.f);
    out[(size_t)k * VN + v] = __expf(x - 30.f) * g_rinv[k];
}

// ---------------- launch ----------------
extern "C" void kernel_launch(void* const* d_in, const int* in_sizes, int n_in,
                              void* d_out, int out_size) {
    const float* we   = (const float*)d_in[0];
    const float* anch = (const float*)d_in[1];
    const float* U    = (const float*)d_in[2];
    const float* p_le = (const float*)d_in[3];
    const float* p_ls = (const float*)d_in[4];
    const float* bias = (const float*)d_in[5];
    const float* Wp   = (const float*)d_in[6];
    float* out = (float*)d_out;

    cudaFuncSetAttribute(k_ubgemm,   cudaFuncAttributeMaxDynamicSharedMemorySize, 51712);
    cudaFuncSetAttribute(k_maingemm, cudaFuncAttributeMaxDynamicSharedMemorySize, 81920);

    k_init<<<(VPAD + 255) / 256, 256>>>();
    k_idcheck<<<576, 256>>>(Wp);
    k_anchors<<<KN, 256>>>(anch, U);
    k_wnorm<<<VPAD / 8, 256>>>(we, Wp);
    k_ubgemm<<<VPAD / 128, 256, 51712>>>(U);

    dim3 gmain(KN / 128, VPAD / 128);
    k_maingemm<<<gmain, 256, 81920>>>(p_le, p_ls, bias);

    for (int it = 0; it < 10; it++) {
        k_rowlin<<<KN, 256>>>();
        k_collin<<<(VN + 255) / 256, 256>>>();
    }
    k_lvlog<<<(VN + 255) / 256, 256>>>();

    k_finalA<<<KN, 256>>>();
    dim3 gf((VN + 255) / 256, KN);
    k_finalB<<<gf, 256>>>(out);
}

// round 7
// speedup vs baseline: 4.5996x; 1.4440x over previous
#include <cuda_runtime.h>
#include <cuda_fp16.h>
#include <math.h>

#define VN 50257
#define VPAD 50304   // 393 * 128
#define KN 512
#define DN 768
#define RN 192
#define KD 960       // DN + RN
#define RSU 40       // ubgemm smem row stride (halves)
#define RSM 72       // maingemm smem row stride (halves), BK=64

// ---------------- scratch (static device globals; no allocation) ----------------
__device__ __half g_A16[KN * KD];
__device__ __half g_B16[(size_t)VPAD * KD];
__device__ float g_AA[KN];
__device__ float g_BB[VPAD];
__device__ float g_base[(size_t)KN * VPAD];   // scale*s + bias - 0.3*mahal ; later exp(x-30)
__device__ float g_K[(size_t)KN * VPAD];      // exp(-mahal/eps); 0 in pad cols
__device__ float g_u[KN];
__device__ float g_v[VPAD];
__device__ float g_lvl[VPAD];
__device__ float g_rinv[KN];
__device__ int   g_idflag;

// ---------------- helpers ----------------
__device__ __forceinline__ void cp16(void* sm, const void* gp) {
    unsigned sa = (unsigned)__cvta_generic_to_shared(sm);
    asm volatile("cp.async.cg.shared.global [%0], [%1], 16;\n" :: "r"(sa), "l"(gp));
}
__device__ __forceinline__ void cpcommit() { asm volatile("cp.async.commit_group;\n"); }
template<int N> __device__ __forceinline__ void cpwait() {
    asm volatile("cp.async.wait_group %0;\n" :: "n"(N));
}
__device__ __forceinline__ void mma16816h(float c[4], const unsigned a[4], const unsigned b[2]) {
    asm volatile(
        "mma.sync.aligned.m16n8k16.row.col.f32.f16.f16.f32 "
        "{%0,%1,%2,%3}, {%4,%5,%6,%7}, {%8,%9}, {%0,%1,%2,%3};\n"
        : "+f"(c[0]), "+f"(c[1]), "+f"(c[2]), "+f"(c[3])
        : "r"(a[0]), "r"(a[1]), "r"(a[2]), "r"(a[3]), "r"(b[0]), "r"(b[1]));
}
__device__ __forceinline__ void ldsm4(unsigned r[4], const __half* p) {
    unsigned a = (unsigned)__cvta_generic_to_shared(p);
    asm volatile("ldmatrix.sync.aligned.m8n8.x4.shared.b16 {%0,%1,%2,%3}, [%4];\n"
                 : "=r"(r[0]), "=r"(r[1]), "=r"(r[2]), "=r"(r[3]) : "r"(a));
}

// ---------------- init ----------------
__global__ void k_init() {
    int i = blockIdx.x * blockDim.x + threadIdx.x;
    if (i < VPAD) g_v[i] = 1.f;
    if (i == 0) g_idflag = 1;
}

__global__ void k_idcheck(const float* __restrict__ Wp) {
    int stride = gridDim.x * blockDim.x;
    for (int i = blockIdx.x * blockDim.x + threadIdx.x; i < DN * DN; i += stride) {
        float e = ((i / DN) == (i % DN)) ? 1.f : 0.f;
        if (Wp[i] != e) g_idflag = 0;
    }
}

// ---------------- anchors: normalize, Ua = a@U, AA from rounded fp16 ----------------
__global__ void k_anchors(const float* __restrict__ anch, const float* __restrict__ U) {
    __shared__ float sa[DN];
    __shared__ float sred[256];
    int k = blockIdx.x, tid = threadIdx.x;

    float ss = 0.f;
    for (int d = tid; d < DN; d += 256) { float x = anch[k * DN + d]; sa[d] = x; ss += x * x; }
    sred[tid] = ss; __syncthreads();
    for (int o = 128; o > 0; o >>= 1) { if (tid < o) sred[tid] += sred[tid + o]; __syncthreads(); }
    float inv = 1.f / fmaxf(sqrtf(sred[0]), 1e-12f);
    __syncthreads();
    float aa = 0.f;
    for (int d = tid; d < DN; d += 256) {
        float x = sa[d] * inv; sa[d] = x;
        __half h = __float2half(x);
        g_A16[k * KD + d] = h;
        float hr = __half2float(h);
        aa += hr * hr;
    }
    __syncthreads();  // sa fully updated
    if (tid < RN) {
        float acc = 0.f;
        for (int d = 0; d < DN; d++) acc += sa[d] * U[d * RN + tid];
        __half h = __float2half(acc);
        g_A16[k * KD + DN + tid] = h;
        float hr = __half2float(h);
        aa += hr * hr;
    }
    sred[tid] = aa; __syncthreads();
    for (int o = 128; o > 0; o >>= 1) { if (tid < o) sred[tid] += sred[tid + o]; __syncthreads(); }
    if (tid == 0) g_AA[k] = sred[0];
}

// ---------------- w_norm: warp-per-row, fp16 out, partial BB = sum w_h^2 ----------------
__global__ __launch_bounds__(256) void k_wnorm(const float* __restrict__ we,
                                               const float* __restrict__ Wp) {
    int warp = threadIdx.x >> 5, lane = threadIdx.x & 31;
    int v = blockIdx.x * 8 + warp;
    if (v >= VPAD) return;
    size_t gb = (size_t)v * KD;
    if (v >= VN) {
        #pragma unroll
        for (int c = 0; c < 6; c++) {
            int d = c * 128 + lane * 4;
            *(uint2*)&g_B16[gb + d] = make_uint2(0u, 0u);
        }
        if (lane == 0) g_BB[v] = 0.f;
        return;
    }
    int flag = g_idflag;
    float4 x[6];
    if (flag) {
        #pragma unroll
        for (int c = 0; c < 6; c++)
            x[c] = *(const float4*)&we[(size_t)v * DN + c * 128 + lane * 4];
    } else {
        for (int c = 0; c < 6; c++) {
            float r[4];
            for (int u2 = 0; u2 < 4; u2++) {
                int d = c * 128 + lane * 4 + u2;
                float acc = 0.f;
                for (int j = 0; j < DN; j++) acc += we[(size_t)v * DN + j] * Wp[d * DN + j];
                r[u2] = acc;
            }
            x[c] = make_float4(r[0], r[1], r[2], r[3]);
        }
    }
    float ss = 0.f;
    #pragma unroll
    for (int c = 0; c < 6; c++)
        ss += x[c].x * x[c].x + x[c].y * x[c].y + x[c].z * x[c].z + x[c].w * x[c].w;
    #pragma unroll
    for (int o = 16; o > 0; o >>= 1) ss += __shfl_xor_sync(0xffffffffu, ss, o);
    float inv = 1.f / fmaxf(sqrtf(ss), 1e-12f);
    float bb = 0.f;
    #pragma unroll
    for (int c = 0; c < 6; c++) {
        int d = c * 128 + lane * 4;
        float vl[4] = {x[c].x * inv, x[c].y * inv, x[c].z * inv, x[c].w * inv};
        __half h[4];
        #pragma unroll
        for (int t = 0; t < 4; t++) {
            h[t] = __float2half(vl[t]);
            float hr = __half2float(h[t]);
            bb += hr * hr;
        }
        *(__half2*)&g_B16[gb + d]     = __half2(h[0], h[1]);
        *(__half2*)&g_B16[gb + d + 2] = __half2(h[2], h[3]);
    }
    #pragma unroll
    for (int o = 16; o > 0; o >>= 1) bb += __shfl_xor_sync(0xffffffffu, bb, o);
    if (lane == 0) g_BB[v] = bb;
}

// ---------------- Ub = w_norm @ U (fp16 single-pass, ldmatrix), fused BB add ----------------
// dyn smem: sW[128*40] + sU[192*40] halves + sBB[128] f32 = 26112 B
__global__ __launch_bounds__(256) void k_ubgemm(const float* __restrict__ U) {
    extern __shared__ __half dsm[];
    __half* sW = dsm;              // 5120 halves
    __half* sU = dsm + 5120;       // 7680 halves
    float* sBB = (float*)(dsm + 12800);

    int bm = blockIdx.x * 128;
    int tid = threadIdx.x;
    int w = tid >> 5, lane = tid & 31;
    int g = lane >> 2, q = lane & 3;
    int wm = w >> 2, wn = w & 3;          // 2 x 4 warps, warp tile 64 x 48
    int mi = lane >> 3, lr = lane & 7;
    int aoff = (wm * 64 + (mi & 1) * 8 + lr) * RSU + (mi >> 1) * 8;
    int boff = (wn * 48 + (mi >> 1) * 8 + lr) * RSU + (mi & 1) * 8;
    if (tid < 128) sBB[tid] = 0.f;

    float acc[4][6][4];
    #pragma unroll
    for (int i = 0; i < 4; i++)
        #pragma unroll
        for (int j = 0; j < 6; j++)
            #pragma unroll
            for (int c = 0; c < 4; c++) acc[i][j][c] = 0.f;

    for (int s = 0; s < 24; s++) {
        int k0 = s * 32;
        __syncthreads();
        for (int c = tid; c < 512; c += 256) {
            int row = c >> 2, ch = c & 3;
            cp16(sW + row * RSU + ch * 8, g_B16 + (size_t)(bm + row) * KD + k0 + ch * 8);
        }
        for (int idx = tid; idx < 32 * RN; idx += 256) {
            int kp = idx / RN, n = idx % RN;
            sU[n * RSU + kp] = __float2half(U[(k0 + kp) * RN + n]);
        }
        cpcommit(); cpwait<0>();
        __syncthreads();

        #pragma unroll
        for (int kk = 0; kk < 32; kk += 16) {
            unsigned ah[4][4], bh[6][2];
            #pragma unroll
            for (int i = 0; i < 4; i++)
                ldsm4(ah[i], sW + aoff + i * 16 * RSU + kk);
            #pragma unroll
            for (int jp = 0; jp < 3; jp++) {
                unsigned t[4];
                ldsm4(t, sU + boff + jp * 16 * RSU + kk);
                bh[2*jp][0] = t[0]; bh[2*jp][1] = t[1];
                bh[2*jp+1][0] = t[2]; bh[2*jp+1][1] = t[3];
            }
            #pragma unroll
            for (int i = 0; i < 4; i++)
                #pragma unroll
                for (int j = 0; j < 6; j++)
                    mma16816h(acc[i][j], ah[i], bh[j]);
        }
    }

    // epilogue: round to fp16, store Ub, accumulate sum of rounded squares
    #pragma unroll
    for (int i = 0; i < 4; i++) {
        int l0 = wm * 64 + i * 16 + g, l1 = l0 + 8;
        size_t m0 = (size_t)(bm + l0) * KD + DN;
        size_t m1 = (size_t)(bm + l1) * KD + DN;
        float p0 = 0.f, p1 = 0.f;
        #pragma unroll
        for (int j = 0; j < 6; j++) {
            int n0 = wn * 48 + j * 8 + 2 * q;
            __half h00 = __float2half(acc[i][j][0]);
            __half h01 = __float2half(acc[i][j][1]);
            __half h10 = __float2half(acc[i][j][2]);
            __half h11 = __float2half(acc[i][j][3]);
            float f00 = __half2float(h00), f01 = __half2float(h01);
            float f10 = __half2float(h10), f11 = __half2float(h11);
            p0 += f00 * f00 + f01 * f01;
            p1 += f10 * f10 + f11 * f11;
            g_B16[m0 + n0] = h00; g_B16[m0 + n0 + 1] = h01;
            g_B16[m1 + n0] = h10; g_B16[m1 + n0 + 1] = h11;
        }
        p0 += __shfl_xor_sync(0xffffffffu, p0, 1); p0 += __shfl_xor_sync(0xffffffffu, p0, 2);
        p1 += __shfl_xor_sync(0xffffffffu, p1, 1); p1 += __shfl_xor_sync(0xffffffffu, p1, 2);
        if (q == 0) { atomicAdd(&sBB[l0], p0); atomicAdd(&sBB[l1], p1); }
    }
    __syncthreads();
    if (tid < 128) g_BB[bm + tid] += sBB[tid];
}

// ---------------- main GEMM (fp16 single-pass, BK=64, dual acc) + fused epilogue ----------------
__device__ __forceinline__ void mg_compute(const __half* sb, int aoff, int boff,
                                           float acc[4][4][4]) {
    const __half* sA = sb;
    const __half* sB = sb + 9216;
    #pragma unroll
    for (int kk = 0; kk < 64; kk += 16) {
        unsigned ah[4][4], bh[4][2];
        #pragma unroll
        for (int i = 0; i < 4; i++)
            ldsm4(ah[i], sA + aoff + i * 16 * RSM + kk);
        #pragma unroll
        for (int jp = 0; jp < 2; jp++) {
            unsigned t[4];
            ldsm4(t, sB + boff + jp * 16 * RSM + kk);
            bh[2*jp][0] = t[0]; bh[2*jp][1] = t[1];
            bh[2*jp+1][0] = t[2]; bh[2*jp+1][1] = t[3];
        }
        #pragma unroll
        for (int i = 0; i < 4; i++)
            #pragma unroll
            for (int j = 0; j < 4; j++)
                mma16816h(acc[i][j], ah[i], bh[j]);
    }
}

// grid (KN/128, VPAD/128); dyn smem = 2 stages * 2 * 128*72 halves = 73728 B
__global__ __launch_bounds__(256) void k_maingemm(const float* __restrict__ p_le,
                                                  const float* __restrict__ p_ls,
                                                  const float* __restrict__ bias) {
    extern __shared__ __half dsm[];
    int bm = blockIdx.x * 128, bn = blockIdx.y * 128;
    int tid = threadIdx.x;
    int w = tid >> 5, lane = tid & 31;
    int g = lane >> 2, q = lane & 3;
    int wm = w >> 2, wn = w & 3;          // 2 x 4 warps, warp tile 64 x 32
    int mi = lane >> 3, lr = lane & 7;
    int aoff = (wm * 64 + (mi & 1) * 8 + lr) * RSM + (mi >> 1) * 8;
    int boff = (wn * 32 + (mi >> 1) * 8 + lr) * RSM + (mi & 1) * 8;

    float accS[4][4][4], accT[4][4][4];
    #pragma unroll
    for (int i = 0; i < 4; i++)
        #pragma unroll
        for (int j = 0; j < 4; j++)
            #pragma unroll
            for (int c = 0; c < 4; c++) { accS[i][j][c] = 0.f; accT[i][j][c] = 0.f; }

    auto load_stage = [&](int s, int buf) {
        __half* base = dsm + buf * 18432;
        int k0 = s * 64;
        for (int c = tid; c < 2048; c += 256) {
            int mtx = c >> 10, wi = c & 1023;
            int row = wi >> 3, ch = wi & 7;
            if (mtx == 0)
                cp16(base + row * RSM + ch * 8,
                     g_A16 + (size_t)(bm + row) * KD + k0 + ch * 8);
            else
                cp16(base + 9216 + row * RSM + ch * 8,
                     g_B16 + (size_t)(bn + row) * KD + k0 + ch * 8);
        }
    };

    load_stage(0, 0); cpcommit();
    for (int s = 0; s < 15; s++) {
        int buf = s & 1;
        if (s < 14) { load_stage(s + 1, buf ^ 1); cpcommit(); cpwait<1>(); }
        else        { cpwait<0>(); }
        __syncthreads();
        if (s < 12) mg_compute(dsm + buf * 18432, aoff, boff, accS);
        else        mg_compute(dsm + buf * 18432, aoff, boff, accT);
        __syncthreads();
    }

    float le = *p_le;
    float eps = ((le > 20.f) ? le : log1pf(expf(le))) + 0.001f;
    float inve = 1.f / eps;
    float scale = fminf(expf(*p_ls), 20.f);

    #pragma unroll
    for (int i = 0; i < 4; i++) {
        int m0 = bm + wm * 64 + i * 16 + g;
        int m1 = m0 + 8;
        float aa0 = g_AA[m0], aa1 = g_AA[m1];
        float bi0 = bias[m0], bi1 = bias[m1];
        #pragma unroll
        for (int j = 0; j < 4; j++) {
            #pragma unroll
            for (int c = 0; c < 2; c++) {
                int v = bn + wn * 32 + j * 8 + 2 * q + c;
                float bb = g_BB[v];
                int inr = (v < VN);
                float sv = accS[i][j][c], ab = sv + accT[i][j][c];
                float mah = fmaxf(aa0 + bb - 2.f * ab, 0.f);
                g_base[(size_t)m0 * VPAD + v] = scale * sv + bi0 - 0.3f * mah;
                g_K[(size_t)m0 * VPAD + v] = inr ? __expf(-mah * inve) : 0.f;
                sv = accS[i][j][c + 2]; ab = sv + accT[i][j][c + 2];
                mah = fmaxf(aa1 + bb - 2.f * ab, 0.f);
                g_base[(size_t)m1 * VPAD + v] = scale * sv + bi1 - 0.3f * mah;
                g_K[(size_t)m1 * VPAD + v] = inr ? __expf(-mah * inve) : 0.f;
            }
        }
    }
}

// ---------------- linear-domain Sinkhorn ----------------
__global__ __launch_bounds__(256) void k_rowlin() {
    int k = blockIdx.x, tid = threadIdx.x;
    const float4* K4 = (const float4*)&g_K[(size_t)k * VPAD];
    const float4* V4 = (const float4*)g_v;
    float s = 0.f;
    for (int i = tid; i < VPAD / 4; i += 256) {
        float4 a = K4[i], b = V4[i];
        s += a.x * b.x + a.y * b.y + a.z * b.z + a.w * b.w;
    }
    __shared__ float sr[256];
    sr[tid] = s; __syncthreads();
    for (int o = 128; o > 0; o >>= 1) { if (tid < o) sr[tid] += sr[tid + o]; __syncthreads(); }
    if (tid == 0) g_u[k] = 1.f / sr[0];
}

__global__ __launch_bounds__(256) void k_collin() {
    __shared__ float su[KN];
    int tid = threadIdx.x;
    for (int i = tid; i < KN; i += 256) su[i] = g_u[i];
    __syncthreads();
    int v = blockIdx.x * 256 + tid;
    if (v >= VN) return;
    const float* col = g_K + v;
    float s0 = 0.f, s1 = 0.f, s2 = 0.f, s3 = 0.f;
    #pragma unroll 4
    for (int k = 0; k < KN; k += 4) {
        s0 += col[(size_t)(k    ) * VPAD] * su[k];
        s1 += col[(size_t)(k + 1) * VPAD] * su[k + 1];
        s2 += col[(size_t)(k + 2) * VPAD] * su[k + 2];
        s3 += col[(size_t)(k + 3) * VPAD] * su[k + 3];
    }
    g_v[v] = 1.f / (s0 + s1 + s2 + s3);
}

__global__ void k_lvlog() {
    int v = blockIdx.x * blockDim.x + threadIdx.x;
    if (v < VN) g_lvl[v] = __logf(g_v[v]);
}

// ---------------- final softmax; finalA writes exp(x-30) in-place ----------------
__global__ __launch_bounds__(256) void k_finalA() {
    int k = blockIdx.x, tid = threadIdx.x;
    float lul = __logf(g_u[k]);
    float* brow = g_base + (size_t)k * VPAD;
    const float* krow = g_K + (size_t)k * VPAD;
    float s = 0.f;
    for (int i = tid; i < 12564; i += 256) {
        float4 b4 = *(const float4*)&brow[i * 4];
        float4 k4 = *(const float4*)&krow[i * 4];
        float4 l4 = *(const float4*)&g_lvl[i * 4];
        float4 e4;
        float x;
        x = b4.x + 0.3f * (__logf(k4.x) + lul + l4.x); x = fminf(fmaxf(x, -30.f), 30.f); e4.x = __expf(x - 30.f);
        x = b4.y + 0.3f * (__logf(k4.y) + lul + l4.y); x = fminf(fmaxf(x, -30.f), 30.f); e4.y = __expf(x - 30.f);
        x = b4.z + 0.3f * (__logf(k4.z) + lul + l4.z); x = fminf(fmaxf(x, -30.f), 30.f); e4.z = __expf(x - 30.f);
        x = b4.w + 0.3f * (__logf(k4.w) + lul + l4.w); x = fminf(fmaxf(x, -30.f), 30.f); e4.w = __expf(x - 30.f);
        s += e4.x + e4.y + e4.z + e4.w;
        *(float4*)&brow[i * 4] = e4;
    }
    if (tid == 0) {  // tail element v = 50256
        float x = brow[50256] + 0.3f * (__logf(krow[50256]) + lul + g_lvl[50256]);
        x = fminf(fmaxf(x, -30.f), 30.f);
        float e = __expf(x - 30.f);
        s += e;
        brow[50256] = e;
    }
    __shared__ float sr[256];
    sr[tid] = s; __syncthreads();
    for (int o = 128; o > 0; o >>= 1) { if (tid < o) sr[tid] += sr[tid + o]; __syncthreads(); }
    if (tid == 0) g_rinv[k] = 1.f / sr[0];
}

__global__ __launch_bounds__(256) void k_finalB(float* __restrict__ out) {
    int k = blockIdx.y;
    int v = blockIdx.x * 256 + threadIdx.x;
    if (v >= VN) return;
    out[(size_t)k * VN + v] = g_base[(size_t)k * VPAD + v] * g_rinv[k];
}

// ---------------- launch ----------------
extern "C" void kernel_launch(void* const* d_in, const int* in_sizes, int n_in,
                              void* d_out, int out_size) {
    const float* we   = (const float*)d_in[0];
    const float* anch = (const float*)d_in[1];
    const float* U    = (const float*)d_in[2];
    const float* p_le = (const float*)d_in[3];
    const float* p_ls = (const float*)d_in[4];
    const float* bias = (const float*)d_in[5];
    const float* Wp   = (const float*)d_in[6];
    float* out = (float*)d_out;

    cudaFuncSetAttribute(k_ubgemm,   cudaFuncAttributeMaxDynamicSharedMemorySize, 26112);
    cudaFuncSetAttribute(k_maingemm, cudaFuncAttributeMaxDynamicSharedMemorySize, 73728);

    k_init<<<(VPAD + 255) / 256, 256>>>();
    k_idcheck<<<576, 256>>>(Wp);
    k_anchors<<<KN, 256>>>(anch, U);
    k_wnorm<<<VPAD / 8, 256>>>(we, Wp);
    k_ubgemm<<<VPAD / 128, 256, 26112>>>(U);

    dim3 gmain(KN / 128, VPAD / 128);
    k_maingemm<<<gmain, 256, 73728>>>(p_le, p_ls, bias);

    for (int it = 0; it < 10; it++) {
        k_rowlin<<<KN, 256>>>();
        k_collin<<<(VN + 255) / 256, 256>>>();
    }
    k_lvlog<<<(VN + 255) / 256, 256>>>();

    k_finalA<<<KN, 256>>>();
    dim3 gf((VN + 255) / 256, KN);
    k_finalB<<<gf, 256>>>(out);
}

// round 8
// speedup vs baseline: 5.7759x; 1.2557x over previous
#include <cuda_runtime.h>
#include <cuda_fp16.h>
#include <math.h>

#define VN 50257
#define VPAD 50304   // 393 * 128
#define KN 512
#define DN 768
#define RN 192
#define KD 960       // DN + RN
#define RSU 40       // ubgemm smem row stride (halves)
#define RSM 72       // maingemm smem row stride (halves), BK=64

// ---------------- scratch (static device globals; no allocation) ----------------
__device__ __half g_A16[KN * KD];
__device__ __half g_B16[(size_t)VPAD * KD];
__device__ float g_AA[KN];
__device__ float g_BB[VPAD];
__device__ float g_F[(size_t)KN * VPAD];      // scale*s + bias - 0.3*mah + 0.3*2ab/eps ; later exp(x-30)
__device__ __half g_Kh[(size_t)KN * VPAD];    // exp(2ab/eps - sh); 0 in pad cols
__device__ float g_u[KN];                      // sinkhorn u-tilde
__device__ float g_v[VPAD];                    // sinkhorn v-tilde (pads = 0)
__device__ float g_vden[2][VPAD];              // col-pass partials
__device__ float g_lvl[VPAD];                  // log(v-tilde)
__device__ float g_rinv[KN];                   // 1/softmax row sum
__device__ int   g_idflag;

// ---------------- helpers ----------------
__device__ __forceinline__ void cp16(void* sm, const void* gp) {
    unsigned sa = (unsigned)__cvta_generic_to_shared(sm);
    asm volatile("cp.async.cg.shared.global [%0], [%1], 16;\n" :: "r"(sa), "l"(gp));
}
__device__ __forceinline__ void cpcommit() { asm volatile("cp.async.commit_group;\n"); }
template<int N> __device__ __forceinline__ void cpwait() {
    asm volatile("cp.async.wait_group %0;\n" :: "n"(N));
}
__device__ __forceinline__ void mma16816h(float c[4], const unsigned a[4], const unsigned b[2]) {
    asm volatile(
        "mma.sync.aligned.m16n8k16.row.col.f32.f16.f16.f32 "
        "{%0,%1,%2,%3}, {%4,%5,%6,%7}, {%8,%9}, {%0,%1,%2,%3};\n"
        : "+f"(c[0]), "+f"(c[1]), "+f"(c[2]), "+f"(c[3])
        : "r"(a[0]), "r"(a[1]), "r"(a[2]), "r"(a[3]), "r"(b[0]), "r"(b[1]));
}
__device__ __forceinline__ void ldsm4(unsigned r[4], const __half* p) {
    unsigned a = (unsigned)__cvta_generic_to_shared(p);
    asm volatile("ldmatrix.sync.aligned.m8n8.x4.shared.b16 {%0,%1,%2,%3}, [%4];\n"
                 : "=r"(r[0]), "=r"(r[1]), "=r"(r[2]), "=r"(r[3]) : "r"(a));
}
__device__ __forceinline__ float eps_of(float le) {
    return ((le > 20.f) ? le : log1pf(expf(le))) + 0.001f;
}

// ---------------- init ----------------
__global__ void k_init() { g_idflag = 1; }

__global__ void k_idcheck(const float* __restrict__ Wp) {
    int stride = gridDim.x * blockDim.x;
    for (int i = blockIdx.x * blockDim.x + threadIdx.x; i < DN * DN; i += stride) {
        float e = ((i / DN) == (i % DN)) ? 1.f : 0.f;
        if (Wp[i] != e) g_idflag = 0;
    }
}

// ---------------- anchors: normalize, Ua = a@U, AA from rounded fp16 ----------------
__global__ void k_anchors(const float* __restrict__ anch, const float* __restrict__ U) {
    __shared__ float sa[DN];
    __shared__ float sred[256];
    int k = blockIdx.x, tid = threadIdx.x;

    float ss = 0.f;
    for (int d = tid; d < DN; d += 256) { float x = anch[k * DN + d]; sa[d] = x; ss += x * x; }
    sred[tid] = ss; __syncthreads();
    for (int o = 128; o > 0; o >>= 1) { if (tid < o) sred[tid] += sred[tid + o]; __syncthreads(); }
    float inv = 1.f / fmaxf(sqrtf(sred[0]), 1e-12f);
    __syncthreads();
    float aa = 0.f;
    for (int d = tid; d < DN; d += 256) {
        float x = sa[d] * inv; sa[d] = x;
        __half h = __float2half(x);
        g_A16[k * KD + d] = h;
        float hr = __half2float(h);
        aa += hr * hr;
    }
    __syncthreads();
    if (tid < RN) {
        float acc = 0.f;
        for (int d = 0; d < DN; d++) acc += sa[d] * U[d * RN + tid];
        __half h = __float2half(acc);
        g_A16[k * KD + DN + tid] = h;
        float hr = __half2float(h);
        aa += hr * hr;
    }
    sred[tid] = aa; __syncthreads();
    for (int o = 128; o > 0; o >>= 1) { if (tid < o) sred[tid] += sred[tid + o]; __syncthreads(); }
    if (tid == 0) g_AA[k] = sred[0];
}

// ---------------- w_norm: warp-per-row, fp16 out, BB = sum of rounded squares ----------------
__global__ __launch_bounds__(256) void k_wnorm(const float* __restrict__ we,
                                               const float* __restrict__ Wp) {
    int warp = threadIdx.x >> 5, lane = threadIdx.x & 31;
    int v = blockIdx.x * 8 + warp;
    if (v >= VPAD) return;
    size_t gb = (size_t)v * KD;
    if (v >= VN) {
        #pragma unroll
        for (int c = 0; c < 6; c++) {
            int d = c * 128 + lane * 4;
            *(uint2*)&g_B16[gb + d] = make_uint2(0u, 0u);
        }
        if (lane == 0) g_BB[v] = 0.f;
        return;
    }
    int flag = g_idflag;
    float4 x[6];
    if (flag) {
        #pragma unroll
        for (int c = 0; c < 6; c++)
            x[c] = *(const float4*)&we[(size_t)v * DN + c * 128 + lane * 4];
    } else {
        for (int c = 0; c < 6; c++) {
            float r[4];
            for (int u2 = 0; u2 < 4; u2++) {
                int d = c * 128 + lane * 4 + u2;
                float acc = 0.f;
                for (int j = 0; j < DN; j++) acc += we[(size_t)v * DN + j] * Wp[d * DN + j];
                r[u2] = acc;
            }
            x[c] = make_float4(r[0], r[1], r[2], r[3]);
        }
    }
    float ss = 0.f;
    #pragma unroll
    for (int c = 0; c < 6; c++)
        ss += x[c].x * x[c].x + x[c].y * x[c].y + x[c].z * x[c].z + x[c].w * x[c].w;
    #pragma unroll
    for (int o = 16; o > 0; o >>= 1) ss += __shfl_xor_sync(0xffffffffu, ss, o);
    float inv = 1.f / fmaxf(sqrtf(ss), 1e-12f);
    float bb = 0.f;
    #pragma unroll
    for (int c = 0; c < 6; c++) {
        int d = c * 128 + lane * 4;
        float vl[4] = {x[c].x * inv, x[c].y * inv, x[c].z * inv, x[c].w * inv};
        __half h[4];
        #pragma unroll
        for (int t = 0; t < 4; t++) {
            h[t] = __float2half(vl[t]);
            float hr = __half2float(h[t]);
            bb += hr * hr;
        }
        *(__half2*)&g_B16[gb + d]     = __half2(h[0], h[1]);
        *(__half2*)&g_B16[gb + d + 2] = __half2(h[2], h[3]);
    }
    #pragma unroll
    for (int o = 16; o > 0; o >>= 1) bb += __shfl_xor_sync(0xffffffffu, bb, o);
    if (lane == 0) g_BB[v] = bb;
}

// ---------------- Ub = w_norm @ U (fp16, ldmatrix), fused BB add ----------------
__global__ __launch_bounds__(256) void k_ubgemm(const float* __restrict__ U) {
    extern __shared__ __half dsm[];
    __half* sW = dsm;              // 5120 halves
    __half* sU = dsm + 5120;       // 7680 halves
    float* sBB = (float*)(dsm + 12800);

    int bm = blockIdx.x * 128;
    int tid = threadIdx.x;
    int w = tid >> 5, lane = tid & 31;
    int g = lane >> 2, q = lane & 3;
    int wm = w >> 2, wn = w & 3;
    int mi = lane >> 3, lr = lane & 7;
    int aoff = (wm * 64 + (mi & 1) * 8 + lr) * RSU + (mi >> 1) * 8;
    int boff = (wn * 48 + (mi >> 1) * 8 + lr) * RSU + (mi & 1) * 8;
    if (tid < 128) sBB[tid] = 0.f;

    float acc[4][6][4];
    #pragma unroll
    for (int i = 0; i < 4; i++)
        #pragma unroll
        for (int j = 0; j < 6; j++)
            #pragma unroll
            for (int c = 0; c < 4; c++) acc[i][j][c] = 0.f;

    for (int s = 0; s < 24; s++) {
        int k0 = s * 32;
        __syncthreads();
        for (int c = tid; c < 512; c += 256) {
            int row = c >> 2, ch = c & 3;
            cp16(sW + row * RSU + ch * 8, g_B16 + (size_t)(bm + row) * KD + k0 + ch * 8);
        }
        for (int idx = tid; idx < 32 * RN; idx += 256) {
            int kp = idx / RN, n = idx % RN;
            sU[n * RSU + kp] = __float2half(U[(k0 + kp) * RN + n]);
        }
        cpcommit(); cpwait<0>();
        __syncthreads();

        #pragma unroll
        for (int kk = 0; kk < 32; kk += 16) {
            unsigned ah[4][4], bh[6][2];
            #pragma unroll
            for (int i = 0; i < 4; i++)
                ldsm4(ah[i], sW + aoff + i * 16 * RSU + kk);
            #pragma unroll
            for (int jp = 0; jp < 3; jp++) {
                unsigned t[4];
                ldsm4(t, sU + boff + jp * 16 * RSU + kk);
                bh[2*jp][0] = t[0]; bh[2*jp][1] = t[1];
                bh[2*jp+1][0] = t[2]; bh[2*jp+1][1] = t[3];
            }
            #pragma unroll
            for (int i = 0; i < 4; i++)
                #pragma unroll
                for (int j = 0; j < 6; j++)
                    mma16816h(acc[i][j], ah[i], bh[j]);
        }
    }

    #pragma unroll
    for (int i = 0; i < 4; i++) {
        int l0 = wm * 64 + i * 16 + g, l1 = l0 + 8;
        size_t m0 = (size_t)(bm + l0) * KD + DN;
        size_t m1 = (size_t)(bm + l1) * KD + DN;
        float p0 = 0.f, p1 = 0.f;
        #pragma unroll
        for (int j = 0; j < 6; j++) {
            int n0 = wn * 48 + j * 8 + 2 * q;
            __half h00 = __float2half(acc[i][j][0]);
            __half h01 = __float2half(acc[i][j][1]);
            __half h10 = __float2half(acc[i][j][2]);
            __half h11 = __float2half(acc[i][j][3]);
            float f00 = __half2float(h00), f01 = __half2float(h01);
            float f10 = __half2float(h10), f11 = __half2float(h11);
            p0 += f00 * f00 + f01 * f01;
            p1 += f10 * f10 + f11 * f11;
            g_B16[m0 + n0] = h00; g_B16[m0 + n0 + 1] = h01;
            g_B16[m1 + n0] = h10; g_B16[m1 + n0 + 1] = h11;
        }
        p0 += __shfl_xor_sync(0xffffffffu, p0, 1); p0 += __shfl_xor_sync(0xffffffffu, p0, 2);
        p1 += __shfl_xor_sync(0xffffffffu, p1, 1); p1 += __shfl_xor_sync(0xffffffffu, p1, 2);
        if (q == 0) { atomicAdd(&sBB[l0], p0); atomicAdd(&sBB[l1], p1); }
    }
    __syncthreads();
    if (tid < 128) g_BB[bm + tid] += sBB[tid];
}

// ---------------- main GEMM (fp16, BK=64, dual acc) + fused epilogue ----------------
__device__ __forceinline__ void mg_compute(const __half* sb, int aoff, int boff,
                                           float acc[4][4][4]) {
    const __half* sA = sb;
    const __half* sB = sb + 9216;
    #pragma unroll
    for (int kk = 0; kk < 64; kk += 16) {
        unsigned ah[4][4], bh[4][2];
        #pragma unroll
        for (int i = 0; i < 4; i++)
            ldsm4(ah[i], sA + aoff + i * 16 * RSM + kk);
        #pragma unroll
        for (int jp = 0; jp < 2; jp++) {
            unsigned t[4];
            ldsm4(t, sB + boff + jp * 16 * RSM + kk);
            bh[2*jp][0] = t[0]; bh[2*jp][1] = t[1];
            bh[2*jp+1][0] = t[2]; bh[2*jp+1][1] = t[3];
        }
        #pragma unroll
        for (int i = 0; i < 4; i++)
            #pragma unroll
            for (int j = 0; j < 4; j++)
                mma16816h(acc[i][j], ah[i], bh[j]);
    }
}

// grid (KN/128, VPAD/128); dyn smem = 2 stages * 2 * 128*72 halves = 73728 B
__global__ __launch_bounds__(256) void k_maingemm(const float* __restrict__ p_le,
                                                  const float* __restrict__ p_ls,
                                                  const float* __restrict__ bias) {
    extern __shared__ __half dsm[];
    int bm = blockIdx.x * 128, bn = blockIdx.y * 128;
    int tid = threadIdx.x;
    int w = tid >> 5, lane = tid & 31;
    int g = lane >> 2, q = lane & 3;
    int wm = w >> 2, wn = w & 3;
    int mi = lane >> 3, lr = lane & 7;
    int aoff = (wm * 64 + (mi & 1) * 8 + lr) * RSM + (mi >> 1) * 8;
    int boff = (wn * 32 + (mi >> 1) * 8 + lr) * RSM + (mi & 1) * 8;

    float accS[4][4][4], accT[4][4][4];
    #pragma unroll
    for (int i = 0; i < 4; i++)
        #pragma unroll
        for (int j = 0; j < 4; j++)
            #pragma unroll
            for (int c = 0; c < 4; c++) { accS[i][j][c] = 0.f; accT[i][j][c] = 0.f; }

    auto load_stage = [&](int s, int buf) {
        __half* base = dsm + buf * 18432;
        int k0 = s * 64;
        for (int c = tid; c < 2048; c += 256) {
            int mtx = c >> 10, wi = c & 1023;
            int row = wi >> 3, ch = wi & 7;
            if (mtx == 0)
                cp16(base + row * RSM + ch * 8,
                     g_A16 + (size_t)(bm + row) * KD + k0 + ch * 8);
            else
                cp16(base + 9216 + row * RSM + ch * 8,
                     g_B16 + (size_t)(bn + row) * KD + k0 + ch * 8);
        }
    };

    load_stage(0, 0); cpcommit();
    for (int s = 0; s < 15; s++) {
        int buf = s & 1;
        if (s < 14) { load_stage(s + 1, buf ^ 1); cpcommit(); cpwait<1>(); }
        else        { cpwait<0>(); }
        __syncthreads();
        if (s < 12) mg_compute(dsm + buf * 18432, aoff, boff, accS);
        else        mg_compute(dsm + buf * 18432, aoff, boff, accT);
        __syncthreads();
    }

    float eps = eps_of(*p_le);
    float inve = 1.f / eps;
    float scale = fminf(expf(*p_ls), 20.f);
    float sh = fmaxf(0.f, 2.f * inve - 9.8f);

    #pragma unroll
    for (int i = 0; i < 4; i++) {
        int m0 = bm + wm * 64 + i * 16 + g;
        int m1 = m0 + 8;
        float aa0 = g_AA[m0], aa1 = g_AA[m1];
        float bi0 = bias[m0], bi1 = bias[m1];
        #pragma unroll
        for (int j = 0; j < 4; j++) {
            #pragma unroll
            for (int c = 0; c < 2; c++) {
                int v = bn + wn * 32 + j * 8 + 2 * q + c;
                float bb = g_BB[v];
                int inr = (v < VN);
                float sv = accS[i][j][c], ab = sv + accT[i][j][c];
                float mah = fmaxf(aa0 + bb - 2.f * ab, 0.f);
                float t2 = 2.f * ab * inve;
                g_F[(size_t)m0 * VPAD + v] = scale * sv + bi0 - 0.3f * mah + 0.3f * t2;
                g_Kh[(size_t)m0 * VPAD + v] = inr ? __float2half(__expf(t2 - sh)) : __float2half(0.f);
                sv = accS[i][j][c + 2]; ab = sv + accT[i][j][c + 2];
                mah = fmaxf(aa1 + bb - 2.f * ab, 0.f);
                t2 = 2.f * ab * inve;
                g_F[(size_t)m1 * VPAD + v] = scale * sv + bi1 - 0.3f * mah + 0.3f * t2;
                g_Kh[(size_t)m1 * VPAD + v] = inr ? __float2half(__expf(t2 - sh)) : __float2half(0.f);
            }
        }
    }
}

// ---------------- sinkhorn init: v-tilde0 = exp(-bb/eps), pads 0 ----------------
__global__ void k_vinit(const float* __restrict__ p_le) {
    int v = blockIdx.x * blockDim.x + threadIdx.x;
    if (v >= VPAD) return;
    float inve = 1.f / eps_of(*p_le);
    g_v[v] = (v < VN) ? __expf(-g_BB[v] * inve) : 0.f;
}

// ---------------- fp16 sinkhorn: row pass ----------------
__global__ __launch_bounds__(256) void k_rowlin() {
    int k = blockIdx.x, tid = threadIdx.x;
    const uint4* K8 = (const uint4*)&g_Kh[(size_t)k * VPAD];
    const float4* V4 = (const float4*)g_v;
    float s = 0.f;
    for (int i = tid; i < VPAD / 8; i += 256) {
        uint4 qq = K8[i];
        float4 a = V4[2 * i], b = V4[2 * i + 1];
        float2 p;
        p = __half22float2(*(__half2*)&qq.x); s += p.x * a.x + p.y * a.y;
        p = __half22float2(*(__half2*)&qq.y); s += p.x * a.z + p.y * a.w;
        p = __half22float2(*(__half2*)&qq.z); s += p.x * b.x + p.y * b.y;
        p = __half22float2(*(__half2*)&qq.w); s += p.x * b.z + p.y * b.w;
    }
    __shared__ float sr[256];
    sr[tid] = s; __syncthreads();
    for (int o = 128; o > 0; o >>= 1) { if (tid < o) sr[tid] += sr[tid + o]; __syncthreads(); }
    if (tid == 0) g_u[k] = 1.f / sr[0];
}

// ---------------- fp16 sinkhorn: col pass (2-way k-split, half2 per thread) ----------------
__global__ __launch_bounds__(256) void k_colpart() {
    __shared__ float su[256];
    int tid = threadIdx.x, cy = blockIdx.y;
    su[tid] = g_u[cy * 256 + tid];
    __syncthreads();
    int v2 = blockIdx.x * 512 + tid * 2;
    if (v2 >= VPAD) return;
    size_t base = (size_t)(cy * 256) * VPAD + v2;
    float sx0 = 0.f, sy0 = 0.f, sx1 = 0.f, sy1 = 0.f;
    #pragma unroll 4
    for (int k = 0; k < 256; k += 2) {
        float2 p0 = __half22float2(*(const __half2*)&g_Kh[base + (size_t)k * VPAD]);
        float2 p1 = __half22float2(*(const __half2*)&g_Kh[base + (size_t)(k + 1) * VPAD]);
        sx0 += p0.x * su[k];     sy0 += p0.y * su[k];
        sx1 += p1.x * su[k + 1]; sy1 += p1.y * su[k + 1];
    }
    *(float2*)&g_vden[cy][v2] = make_float2(sx0 + sx1, sy0 + sy1);
}

__global__ void k_vfin() {
    int v = blockIdx.x * blockDim.x + threadIdx.x;
    if (v >= VPAD) return;
    float den = g_vden[0][v] + g_vden[1][v];
    g_v[v] = (v < VN) ? 1.f / den : 0.f;
}

__global__ void k_lvlog() {
    int v = blockIdx.x * blockDim.x + threadIdx.x;
    if (v < VN) g_lvl[v] = __logf(g_v[v]);
}

// ---------------- final softmax; finalA writes exp(x-30) in-place into g_F ----------------
__global__ __launch_bounds__(256) void k_finalA(const float* __restrict__ p_le) {
    int k = blockIdx.x, tid = threadIdx.x;
    float inve = 1.f / eps_of(*p_le);
    float sh = fmaxf(0.f, 2.f * inve - 9.8f);
    float cs = 0.3f * (__logf(g_u[k]) - sh);
    float* frow = g_F + (size_t)k * VPAD;
    float s = 0.f;
    for (int i = tid; i < 12564; i += 256) {
        float4 f4 = *(const float4*)&frow[i * 4];
        float4 l4 = *(const float4*)&g_lvl[i * 4];
        float4 e4;
        float x;
        x = f4.x + cs + 0.3f * l4.x; x = fminf(fmaxf(x, -30.f), 30.f); e4.x = __expf(x - 30.f);
        x = f4.y + cs + 0.3f * l4.y; x = fminf(fmaxf(x, -30.f), 30.f); e4.y = __expf(x - 30.f);
        x = f4.z + cs + 0.3f * l4.z; x = fminf(fmaxf(x, -30.f), 30.f); e4.z = __expf(x - 30.f);
        x = f4.w + cs + 0.3f * l4.w; x = fminf(fmaxf(x, -30.f), 30.f); e4.w = __expf(x - 30.f);
        s += e4.x + e4.y + e4.z + e4.w;
        *(float4*)&frow[i * 4] = e4;
    }
    if (tid == 0) {  // tail element v = 50256
        float x = frow[50256] + cs + 0.3f * g_lvl[50256];
        x = fminf(fmaxf(x, -30.f), 30.f);
        float e = __expf(x - 30.f);
        s += e;
        frow[50256] = e;
    }
    __shared__ float sr[256];
    sr[tid] = s; __syncthreads();
    for (int o = 128; o > 0; o >>= 1) { if (tid < o) sr[tid] += sr[tid + o]; __syncthreads(); }
    if (tid == 0) g_rinv[k] = 1.f / sr[0];
}

__global__ __launch_bounds__(256) void k_finalB(float* __restrict__ out) {
    int k = blockIdx.y;
    int v = blockIdx.x * 256 + threadIdx.x;
    if (v >= VN) return;
    out[(size_t)k * VN + v] = g_F[(size_t)k * VPAD + v] * g_rinv[k];
}

// ---------------- launch ----------------
extern "C" void kernel_launch(void* const* d_in, const int* in_sizes, int n_in,
                              void* d_out, int out_size) {
    const float* we   = (const float*)d_in[0];
    const float* anch = (const float*)d_in[1];
    const float* U    = (const float*)d_in[2];
    const float* p_le = (const float*)d_in[3];
    const float* p_ls = (const float*)d_in[4];
    const float* bias = (const float*)d_in[5];
    const float* Wp   = (const float*)d_in[6];
    float* out = (float*)d_out;

    cudaFuncSetAttribute(k_ubgemm,   cudaFuncAttributeMaxDynamicSharedMemorySize, 26112);
    cudaFuncSetAttribute(k_maingemm, cudaFuncAttributeMaxDynamicSharedMemorySize, 73728);

    k_init<<<1, 1>>>();
    k_idcheck<<<576, 256>>>(Wp);
    k_anchors<<<KN, 256>>>(anch, U);
    k_wnorm<<<VPAD / 8, 256>>>(we, Wp);
    k_ubgemm<<<VPAD / 128, 256, 26112>>>(U);

    dim3 gmain(KN / 128, VPAD / 128);
    k_maingemm<<<gmain, 256, 73728>>>(p_le, p_ls, bias);

    k_vinit<<<(VPAD + 255) / 256, 256>>>(p_le);
    dim3 gcol((VPAD + 511) / 512, 2);
    for (int it = 0; it < 10; it++) {
        k_rowlin<<<KN, 256>>>();
        k_colpart<<<gcol, 256>>>();
        k_vfin<<<(VPAD + 255) / 256, 256>>>();
    }
    k_lvlog<<<(VN + 255) / 256, 256>>>();

    k_finalA<<<KN, 256>>>(p_le);
    dim3 gf((VN + 255) / 256, KN);
    k_finalB<<<gf, 256>>>(out);
}